// round 11
// baseline (speedup 1.0000x reference)
#include <cuda_runtime.h>
#include <stdint.h>

// Problem constants (fixed by dataset)
#define S_TOK   16384
#define C_DIM   1280
#define C3      3840
#define D_HEAD  80
#define BLK     16
#define NBLK    (S_TOK / BLK)   // 1024
#define KDIM    1280
#define KB8     (KDIM / 8)      // 160

// Scratch (__device__ globals; 128B-aligned for cp.async.bulk sources)
__device__ float    g_qkv[(size_t)S_TOK * C3];
__device__ __align__(128) uint32_t g_xt [(size_t)S_TOK * KDIM];         // x gathered+tf32, A-frag
__device__ __align__(128) uint32_t g_y  [(size_t)S_TOK * KDIM];         // attn out tf32, A-frag
__device__ __align__(128) uint32_t g_wqkvF [(size_t)(C3   / 64) * KB8 * 832];
__device__ __align__(128) uint32_t g_wprojF[(size_t)(C_DIM / 64) * KB8 * 832];

// ---------------------------------------------------------------------------
__device__ __forceinline__ uint32_t f2tf(float f) {
    uint32_t r; asm("cvt.rna.tf32.f32 %0, %1;" : "=r"(r) : "f"(f)); return r;
}
// A-fragment layout (any M, K=1280):
__device__ __forceinline__ size_t addrA(int m, int k) {
    return ((size_t)((m >> 4) * KB8 + (k >> 3)) << 7)
         + ((m & 7) << 4) + ((k & 3) << 2) + (((k >> 2) & 1) << 1) + ((m >> 3) & 1);
}
// B-fragment layout (weights K x N, K=1280):
__device__ __forceinline__ size_t addrB(int k, int n) {
    return (size_t)((n >> 6) * KB8 + (k >> 3)) * 832
         + (size_t)(k & 7) * 104 + (n & 7) * 12 + ((n >> 3) & 7);
}
__device__ __forceinline__ uint32_t smem_u32(const void* p) {
    uint32_t a;
    asm("{ .reg .u64 t; cvta.to.shared.u64 t, %1; cvt.u32.u64 %0, t; }" : "=r"(a) : "l"(p));
    return a;
}
// Bulk async copy gmem->smem, completion feeds mbarrier tx-count
__device__ __forceinline__ void bulk_g2s(uint32_t dst, const void* src,
                                         uint32_t bytes, uint32_t mbar) {
    asm volatile(
        "cp.async.bulk.shared::cluster.global.mbarrier::complete_tx::bytes "
        "[%0], [%1], %2, [%3];"
        :: "r"(dst), "l"(src), "r"(bytes), "r"(mbar) : "memory");
}
#define MBARRIER_INIT(addr, cnt) \
    asm volatile("mbarrier.init.shared.b64 [%0], %1;" :: "r"(addr), "r"(cnt) : "memory")
#define MBARRIER_EXPECT_TX(addr, tx) \
    asm volatile("mbarrier.arrive.expect_tx.shared.b64 _, [%0], %1;" \
                 :: "r"(addr), "r"(tx) : "memory")
#define MBARRIER_WAIT_PARITY(addr, par) do {                                   \
    uint32_t _mb = (addr); uint32_t _p = (par); uint32_t _done;                \
    asm volatile("{\n\t.reg .pred p;\n\t"                                      \
        "mbarrier.try_wait.parity.acquire.cta.shared::cta.b64 p, [%1], %2;\n\t"\
        "selp.b32 %0, 1, 0, p;\n\t}"                                           \
        : "=r"(_done) : "r"(_mb), "r"(_p) : "memory");                         \
    if (!_done) {                                                              \
        asm volatile("{\n\t.reg .pred P1;\n\t"                                 \
            "WL_%=:\n\t"                                                       \
            "mbarrier.try_wait.parity.acquire.cta.shared::cta.b64 P1, [%0], %1, 0x989680;\n\t" \
            "@P1 bra.uni WD_%=;\n\t"                                           \
            "bra.uni WL_%=;\n\t"                                               \
            "WD_%=:\n\t}"                                                      \
            :: "r"(_mb), "r"(_p) : "memory");                                  \
    }                                                                          \
} while (0)

__device__ __forceinline__ void mma_tf32(float* d, const uint32_t* a, const uint32_t* b) {
    asm volatile(
        "mma.sync.aligned.m16n8k8.row.col.f32.tf32.tf32.f32 "
        "{%0,%1,%2,%3}, {%4,%5,%6,%7}, {%8,%9}, {%0,%1,%2,%3};"
        : "+f"(d[0]), "+f"(d[1]), "+f"(d[2]), "+f"(d[3])
        : "r"(a[0]), "r"(a[1]), "r"(a[2]), "r"(a[3]),
          "r"(b[0]), "r"(b[1]));
}

// ---------------------------------------------------------------------------
// TF32 mma.sync GEMM, fragment-native smem (all frag loads = LDS.128).
// CTA 128x128, BK=16, 128 thr (4 warps 2x2), warp tile 64x64.
// 4-stage pipeline fed by cp.async.bulk (10 bulk copies/stage, thread 0 only),
// mbarrier expect_tx completion. 2 CTAs/SM.
// ---------------------------------------------------------------------------
#define BM 128
#define BN 128
#define BK 16
#define A_STAGE_W 2048
#define B_STAGE_W 3328
#define ST_W (A_STAGE_W + B_STAGE_W)     // 5376 words
#define NSTAGE 4
#define MB_OFF (NSTAGE * ST_W * 4)       // 86016: 4 mbarriers
#define SMEM_BYTES (MB_OFF + 64)

__global__ __launch_bounds__(128, 2)
void mma_gemm_frag(const uint32_t* __restrict__ A, const uint32_t* __restrict__ B,
                   float* __restrict__ C, int N)
{
    extern __shared__ char smem[];
    const uint32_t sb = smem_u32(smem);
    uint32_t* smw = (uint32_t*)smem;

    const int tid  = threadIdx.x;
    const int bx   = blockIdx.x, by = blockIdx.y;
    const int warp = tid >> 5, lane = tid & 31;
    const int wm   = warp >> 1, wn = warp & 1;   // 2x2 warp grid
    const int g    = lane >> 2, t = lane & 3;

    const uint32_t mb = sb + (uint32_t)MB_OFF;

    if (tid == 0) {
        #pragma unroll
        for (int s = 0; s < NSTAGE; s++) MBARRIER_INIT(mb + 8 * s, 1);
    }
    __syncthreads();

    // gmem stage bases for this CTA
    const uint32_t* Abase = A + (size_t)(by * 8) * KB8 * 128;
    const uint32_t* Bbase = B + (size_t)(bx * 2) * KB8 * 832;

    // consumer fragment bases (word offsets within a stage)
    const uint32_t a_base = (uint32_t)(wm * 1024 + g * 16 + t * 4);
    const uint32_t b_base = (uint32_t)(A_STAGE_W + wn * 1664 + t * 104 + g * 12);

    float acc[4][8][4];
    #pragma unroll
    for (int mt = 0; mt < 4; mt++)
        #pragma unroll
        for (int nt = 0; nt < 8; nt++)
            #pragma unroll
            for (int i = 0; i < 4; i++) acc[mt][nt][i] = 0.f;

    const int NIT = KDIM / BK;   // 80

    // prologue: stages 0..2 <- tiles 0..2 (thread 0 only)
    if (tid == 0) {
        #pragma unroll
        for (int s = 0; s < NSTAGE - 1; s++) {
            const uint32_t fmb = mb + 8 * s;
            const uint32_t so  = sb + s * (ST_W * 4);
            const int kt8 = s * 2;
            MBARRIER_EXPECT_TX(fmb, ST_W * 4);
            #pragma unroll
            for (int rg = 0; rg < 8; rg++)
                bulk_g2s(so + rg * 1024,
                         Abase + (size_t)rg * KB8 * 128 + kt8 * 128, 1024, fmb);
            #pragma unroll
            for (int ngl = 0; ngl < 2; ngl++)
                bulk_g2s(so + A_STAGE_W * 4 + ngl * 6656,
                         Bbase + (size_t)ngl * KB8 * 832 + kt8 * 832, 6656, fmb);
        }
    }

    for (int i = 0; i < NIT; i++) {
        const int s = i & 3;

        // issue tile i+3 into stage (i+3)&3 == (i-1)&3 (reads done: end-of-(i-1) sync)
        if (tid == 0 && i + NSTAGE - 1 < NIT) {
            const int s3 = (i + NSTAGE - 1) & 3;
            const uint32_t fmb = mb + 8 * s3;
            const uint32_t so  = sb + s3 * (ST_W * 4);
            const int kt8 = (i + NSTAGE - 1) * 2;
            MBARRIER_EXPECT_TX(fmb, ST_W * 4);
            #pragma unroll
            for (int rg = 0; rg < 8; rg++)
                bulk_g2s(so + rg * 1024,
                         Abase + (size_t)rg * KB8 * 128 + kt8 * 128, 1024, fmb);
            #pragma unroll
            for (int ngl = 0; ngl < 2; ngl++)
                bulk_g2s(so + A_STAGE_W * 4 + ngl * 6656,
                         Bbase + (size_t)ngl * KB8 * 832 + kt8 * 832, 6656, fmb);
        }

        // wait for stage s (phase flips every NSTAGE uses)
        MBARRIER_WAIT_PARITY(mb + 8 * s, (i >> 2) & 1);

        // ---- compute: 2 k8 steps, all fragment loads are LDS.128 ----
        const uint32_t* As = smw + s * ST_W + a_base;
        const uint32_t* Bb = smw + s * ST_W + b_base;

        #pragma unroll
        for (int ks8 = 0; ks8 < 2; ks8++) {
            uint32_t af[4][4];
            #pragma unroll
            for (int mt = 0; mt < 4; mt++)
                *(uint4*)af[mt] = *(const uint4*)(As + mt * 256 + ks8 * 128);
            uint32_t bf0[8], bf1[8];
            {
                const uint32_t* p0 = Bb + ks8 * 832;
                *(uint4*)&bf0[0] = *(const uint4*)(p0);
                *(uint4*)&bf0[4] = *(const uint4*)(p0 + 4);
                *(uint4*)&bf1[0] = *(const uint4*)(p0 + 416);
                *(uint4*)&bf1[4] = *(const uint4*)(p0 + 420);
            }
            #pragma unroll
            for (int mt = 0; mt < 4; mt++)
                #pragma unroll
                for (int nt = 0; nt < 8; nt++) {
                    uint32_t bb[2] = { bf0[nt], bf1[nt] };
                    mma_tf32(acc[mt][nt], af[mt], bb);
                }
        }

        __syncthreads();   // all reads of stage s done -> safe to overwrite at i+1
    }

    // ---- epilogue (row-major C) ----
    #pragma unroll
    for (int mt = 0; mt < 4; mt++) {
        const int row0 = by * BM + wm * 64 + mt * 16 + g;
        #pragma unroll
        for (int nt = 0; nt < 8; nt++) {
            const int col = bx * BN + wn * 64 + nt * 8 + t * 2;
            *(float2*)(C + (size_t)row0 * N + col) =
                make_float2(acc[mt][nt][0], acc[mt][nt][1]);
            *(float2*)(C + (size_t)(row0 + 8) * N + col) =
                make_float2(acc[mt][nt][2], acc[mt][nt][3]);
        }
    }
}

// ---------------------------------------------------------------------------
// x -> gathered rows, tf32, A-fragment layout
// ---------------------------------------------------------------------------
__global__ __launch_bounds__(256)
void cvt_x_gather_kernel(const float* __restrict__ x, uint32_t* __restrict__ xt,
                         const int* __restrict__ win)
{
    int i = blockIdx.x * 256 + threadIdx.x;
    int s  = i / (KDIM / 4);
    int c4 = (i % (KDIM / 4)) * 4;
    float4 v = *(const float4*)(x + (size_t)win[s] * KDIM + c4);
    size_t a0 = addrA(s, c4);
    xt[a0 +  0] = f2tf(v.x);
    xt[a0 +  4] = f2tf(v.y);
    xt[a0 +  8] = f2tf(v.z);
    xt[a0 + 12] = f2tf(v.w);
}

// ---------------------------------------------------------------------------
// W[K,N] fp32 row-major -> tf32 B-fragment layout
// ---------------------------------------------------------------------------
__global__ __launch_bounds__(256)
void cvt_w_frag_kernel(const float* __restrict__ W, uint32_t* __restrict__ WF, int N)
{
    int i = blockIdx.x * 256 + threadIdx.x;
    int k  = i / (N / 4);
    int n4 = (i % (N / 4)) * 4;
    float4 v = *(const float4*)(W + (size_t)k * N + n4);
    WF[addrB(k, n4 + 0)] = f2tf(v.x);
    WF[addrB(k, n4 + 1)] = f2tf(v.y);
    WF[addrB(k, n4 + 2)] = f2tf(v.z);
    WF[addrB(k, n4 + 3)] = f2tf(v.w);
}

// ---------------------------------------------------------------------------
// Windowed attention, RoPE fused; scatters y (tf32) into A-frag layout,
// rows in ORIGINAL token order (feeds GEMM2 directly).
// ---------------------------------------------------------------------------
__global__ __launch_bounds__(256)
void attn_kernel(const float* __restrict__ qkv, uint32_t* __restrict__ y,
                 const int* __restrict__ win,
                 const float* __restrict__ cosp, const float* __restrict__ sinp)
{
    const int b = blockIdx.x >> 4;
    const int h = blockIdx.x & 15;

    __shared__ float qs[BLK][D_HEAD + 1];
    __shared__ float ks[BLK][D_HEAD + 1];
    __shared__ float vs[BLK][D_HEAD + 1];
    __shared__ float att[BLK][BLK + 1];
    __shared__ int   toks[BLK];

    const int tid = threadIdx.x;
    if (tid < BLK) toks[tid] = win[b * BLK + tid];
    __syncthreads();

    for (int tdx = tid; tdx < BLK * D_HEAD; tdx += 256) {
        int i = tdx / D_HEAD, d = tdx % D_HEAD;
        size_t base = (size_t)(b * BLK + i) * C3 + (size_t)h * D_HEAD + d;
        float q = qkv[base];
        float k = qkv[base + C_DIM];
        float v = qkv[base + 2 * C_DIM];
        int tok = toks[i];
        float cv = cosp[(size_t)tok * D_HEAD + d];
        float sv = sinp[(size_t)tok * D_HEAD + d];
        qs[i][d] = q * cv + k * sv;
        ks[i][d] = k * cv - q * sv;
        vs[i][d] = v;
    }
    __syncthreads();

    {
        int i = tid >> 4, j = tid & 15;
        float sc = 0.f;
        #pragma unroll
        for (int d = 0; d < D_HEAD; d++) sc += qs[i][d] * ks[j][d];
        att[i][j] = sc * 0.11180339887498949f;   // 1/sqrt(80)
    }
    __syncthreads();

    if (tid < BLK) {
        float m = -1e30f;
        #pragma unroll
        for (int j = 0; j < BLK; j++) m = fmaxf(m, att[tid][j]);
        float sum = 0.f;
        #pragma unroll
        for (int j = 0; j < BLK; j++) {
            float e = __expf(att[tid][j] - m);
            att[tid][j] = e;
            sum += e;
        }
        float inv = 1.f / sum;
        #pragma unroll
        for (int j = 0; j < BLK; j++) att[tid][j] *= inv;
    }
    __syncthreads();

    for (int tdx = tid; tdx < BLK * D_HEAD; tdx += 256) {
        int i = tdx / D_HEAD, d = tdx % D_HEAD;
        float a = 0.f;
        #pragma unroll
        for (int j = 0; j < BLK; j++) a += att[i][j] * vs[j][d];
        y[addrA(toks[i], h * D_HEAD + d)] = f2tf(a);
    }
}

// ---------------------------------------------------------------------------
extern "C" void kernel_launch(void* const* d_in, const int* in_sizes, int n_in,
                              void* d_out, int out_size)
{
    const float* x     = (const float*)d_in[0];
    const float* cosp  = (const float*)d_in[1];
    const float* sinp  = (const float*)d_in[2];
    const float* Wqkv  = (const float*)d_in[3];
    const float* Wproj = (const float*)d_in[4];
    const int*   win   = (const int*)  d_in[5];
    float* out = (float*)d_out;

    float *qkv_ptr;
    uint32_t *xt_ptr, *y_ptr, *wqkv_ptr, *wproj_ptr;
    cudaGetSymbolAddress((void**)&qkv_ptr,   g_qkv);
    cudaGetSymbolAddress((void**)&xt_ptr,    g_xt);
    cudaGetSymbolAddress((void**)&y_ptr,     g_y);
    cudaGetSymbolAddress((void**)&wqkv_ptr,  g_wqkvF);
    cudaGetSymbolAddress((void**)&wproj_ptr, g_wprojF);

    cudaFuncSetAttribute(mma_gemm_frag,
        cudaFuncAttributeMaxDynamicSharedMemorySize, SMEM_BYTES);

    // 0) pre-permute inputs: x (gather + tf32 + A-frag), weights (tf32 + B-frag)
    cvt_x_gather_kernel<<<(S_TOK * (KDIM / 4)) / 256, 256>>>(x, xt_ptr, win);
    cvt_w_frag_kernel<<<(KDIM * (C3 / 4)) / 256, 256>>>(Wqkv, wqkv_ptr, C3);
    cvt_w_frag_kernel<<<(KDIM * (C_DIM / 4)) / 256, 256>>>(Wproj, wproj_ptr, C_DIM);

    // 1) QKV GEMM: g_qkv = g_xt @ W_qkv   (gather already applied)
    {
        dim3 grid(C3 / BN, S_TOK / BM);   // 30 x 128
        mma_gemm_frag<<<grid, 128, SMEM_BYTES>>>(xt_ptr, wqkv_ptr, qkv_ptr, C3);
    }

    // 2) Windowed attention (RoPE fused) -> g_y (A-frag layout, original order)
    attn_kernel<<<NBLK * 16, 256>>>(qkv_ptr, y_ptr, win, cosp, sinp);

    // 3) Output projection: out = g_y @ W_proj
    {
        dim3 grid(C_DIM / BN, S_TOK / BM);  // 10 x 128
        mma_gemm_frag<<<grid, 128, SMEM_BYTES>>>(y_ptr, wproj_ptr, out, C_DIM);
    }
}

// round 12
// speedup vs baseline: 1.7507x; 1.7507x over previous
#include <cuda_runtime.h>
#include <cuda_fp16.h>
#include <stdint.h>

// Problem constants (fixed by dataset)
#define S_TOK   16384
#define C_DIM   1280
#define C3      3840
#define D_HEAD  80
#define BLK     16
#define NBLK    (S_TOK / BLK)   // 1024
#define KDIM    1280
#define KT16    (KDIM / 16)     // 80 k-tiles of 16

// Scratch (__device__ globals; no allocation allowed)
__device__ float g_qkv[(size_t)S_TOK * C3];                         // GEMM1 out (fp32)
__device__ __align__(128) __half g_xt [(size_t)S_TOK * KDIM];       // x gathered, fp16 A-frag
__device__ __align__(128) __half g_y  [(size_t)S_TOK * KDIM];       // attn out, fp16 A-frag
__device__ __align__(128) __half g_wqkvF [(size_t)C3   * KDIM];     // W_qkv  fp16 B-frag
__device__ __align__(128) __half g_wprojF[(size_t)C_DIM * KDIM];    // W_proj fp16 B-frag

// ---------------------------------------------------------------------------
// fp16 A-fragment layout for mma.m16n8k16 (element index in __half units):
//   tile (16m x 16k) = 256 halfs; lane l=(m&7)*4+((k>>1)&3) owns 8 halfs
//   (one uint4 = a0..a3 in order), r = ((m>>3)&1) + ((k>>3)&1)*2, e = k&1.
__device__ __forceinline__ size_t addrA16(int m, int k) {
    int l = (m & 7) * 4 + ((k >> 1) & 3);
    int r = ((m >> 3) & 1) + ((k >> 3) & 1) * 2;
    return ((size_t)((m >> 4) * KT16 + (k >> 4)) << 8) + l * 8 + r * 2 + (k & 1);
}
// fp16 B-fragment layout (weights K x N): block (16k x 64n) = 1024 halfs.
//   kk: t=(kk>>1)&3, h=(kk>>3)&1, e=kk&1 ; nn: g=(nn&7)^(kk&6) [swizzle],
//   q=(nn>>5)&1, c=(nn>>3)&3. uint4 per (t,h,q,g) = b-regs for nt=q*4..q*4+3.
__device__ __forceinline__ size_t addrB16(int k, int n) {
    int kk = k & 15, nn = n & 63;
    int t = (kk >> 1) & 3, h = (kk >> 3) & 1, e = kk & 1;
    int g = (nn & 7) ^ (kk & 6);
    int q = (nn >> 5) & 1, c = (nn >> 3) & 3;
    return (size_t)((n >> 6) * KT16 + (k >> 4)) * 1024
         + (size_t)((((t * 2 + h) * 2 + q) * 8 + g) * 8 + c * 2 + e);
}
__device__ __forceinline__ uint32_t smem_u32(const void* p) {
    uint32_t a;
    asm("{ .reg .u64 t; cvta.to.shared.u64 t, %1; cvt.u32.u64 %0, t; }" : "=r"(a) : "l"(p));
    return a;
}
__device__ __forceinline__ void cpa16(uint32_t dst, const void* src) {
    asm volatile("cp.async.cg.shared.global [%0], [%1], 16;" :: "r"(dst), "l"(src) : "memory");
}
__device__ __forceinline__ void cpa_commit() {
    asm volatile("cp.async.commit_group;" ::: "memory");
}
__device__ __forceinline__ void cpa_wait2() {
    asm volatile("cp.async.wait_group 2;" ::: "memory");
}
__device__ __forceinline__ void mma_f16(float* d, const uint32_t* a, const uint32_t* b) {
    asm volatile(
        "mma.sync.aligned.m16n8k16.row.col.f32.f16.f16.f32 "
        "{%0,%1,%2,%3}, {%4,%5,%6,%7}, {%8,%9}, {%0,%1,%2,%3};"
        : "+f"(d[0]), "+f"(d[1]), "+f"(d[2]), "+f"(d[3])
        : "r"(a[0]), "r"(a[1]), "r"(a[2]), "r"(a[3]),
          "r"(b[0]), "r"(b[1]));
}

// ---------------------------------------------------------------------------
// FP16 mma.sync GEMM, fragment-native smem (all frag loads = LDS.128).
// CTA 128x128, BK=32 (2 k16 steps), 128 thr (4 warps 2x2), warp tile 64x64.
// 4-stage cp.async pipeline, 1 sync/iter, 2 CTAs/SM.
// A: fp16 A-frag [M,1280]. B: fp16 B-frag [1280,N]. C: fp32 row-major.
// smem/stage: A 8192B + B 8192B = 16KB.
// ---------------------------------------------------------------------------
#define BM 128
#define BN 128
#define BK 32
#define A_STAGE_W 2048                   // words (8KB)
#define B_STAGE_W 2048                   // words (8KB)
#define ST_W (A_STAGE_W + B_STAGE_W)     // 4096 words / stage
#define NSTAGE 4
#define SMEM_BYTES (NSTAGE * ST_W * 4)   // 65536

__global__ __launch_bounds__(128, 2)
void mma_gemm_h(const __half* __restrict__ A, const __half* __restrict__ B,
                float* __restrict__ C, int N)
{
    extern __shared__ char smem[];
    const uint32_t sb = smem_u32(smem);
    uint32_t* smw = (uint32_t*)smem;

    const int tid  = threadIdx.x;
    const int bx   = blockIdx.x, by = blockIdx.y;
    const int warp = tid >> 5, lane = tid & 31;
    const int wm   = warp >> 1, wn = warp & 1;   // 2x2 warp grid
    const int g    = lane >> 2, t = lane & 3;

    // ---- producer mapping: 8 cpa16 / thread / stage ----
    // A: positions p = tid + 128*j (j=0..3); 512B chunk ca=p>>5: rg=ca>>1, jk=ca&1
    const __half* Asrc[4];
    uint32_t a_dst[4];
    #pragma unroll
    for (int j = 0; j < 4; j++) {
        int p  = tid + 128 * j;
        int ca = p >> 5;                 // 0..15
        int rg = ca >> 1, jk = ca & 1;
        Asrc[j] = A + ((size_t)(by * 8 + rg) * KT16 + jk) * 256 + (p & 31) * 8;
        a_dst[j] = (uint32_t)p * 16;
    }
    // B: chunk j (2048B): ngl=j>>1, jk=j&1 ; within = tid*16B
    const __half* Bsrc[4];
    uint32_t b_dst[4];
    #pragma unroll
    for (int j = 0; j < 4; j++) {
        int ngl = j >> 1, jk = j & 1;
        Bsrc[j] = B + ((size_t)(bx * 2 + ngl) * KT16 + jk) * 1024 + tid * 8;
        b_dst[j] = (uint32_t)(A_STAGE_W * 4) + (uint32_t)(j * 2048 + tid * 16);
    }
    // per-iter gmem advance: A +512 halfs (2 k-tiles), B +2048 halfs

    // ---- consumer fragment bases (word offsets within a stage) ----
    //   A frag (mt, ks): ((wm*4+mt)*2+ks)*128 + lane*4        (one uint4)
    //   B frag (ks,h,q): A_STAGE_W + (wn*2+ks)*512 + (t*32+h*16+q*8+(g^(2t)))*4
    const uint32_t a_base = (uint32_t)(lane * 4);
    const int gs = g ^ (2 * t);
    const uint32_t b_base = (uint32_t)(A_STAGE_W + t * 128 + gs * 4);

    float acc[4][8][4];
    #pragma unroll
    for (int mt = 0; mt < 4; mt++)
        #pragma unroll
        for (int nt = 0; nt < 8; nt++)
            #pragma unroll
            for (int i = 0; i < 4; i++) acc[mt][nt][i] = 0.f;

    const int NIT = KDIM / BK;   // 40

    // ---- prologue: issue stages 0..2 ----
    #pragma unroll
    for (int s = 0; s < NSTAGE - 1; s++) {
        const uint32_t so = sb + s * (ST_W * 4);
        #pragma unroll
        for (int j = 0; j < 4; j++)
            cpa16(so + a_dst[j], Asrc[j] + (size_t)s * 512);
        #pragma unroll
        for (int j = 0; j < 4; j++)
            cpa16(so + b_dst[j], Bsrc[j] + (size_t)s * 2048);
        cpa_commit();
    }

    for (int i = 0; i < NIT; i++) {
        const int s = i & 3;
        cpa_wait2();          // group i complete -> stage i%4 ready
        __syncthreads();      // + reads of stage (i-1)%4 done

        if (i + NSTAGE - 1 < NIT) {
            const int s3 = (i + NSTAGE - 1) & 3;
            const uint32_t so = sb + s3 * (ST_W * 4);
            const size_t ko = (size_t)(i + NSTAGE - 1);
            #pragma unroll
            for (int j = 0; j < 4; j++)
                cpa16(so + a_dst[j], Asrc[j] + ko * 512);
            #pragma unroll
            for (int j = 0; j < 4; j++)
                cpa16(so + b_dst[j], Bsrc[j] + ko * 2048);
        }
        cpa_commit();

        // ---- compute: 2 k16 steps ----
        const uint32_t* As = smw + s * ST_W;
        #pragma unroll
        for (int ks = 0; ks < 2; ks++) {
            uint32_t af[4][4];
            #pragma unroll
            for (int mt = 0; mt < 4; mt++)
                *(uint4*)af[mt] = *(const uint4*)
                    (As + ((wm * 4 + mt) * 2 + ks) * 128 + a_base);
            uint32_t b0[8], b1[8];     // b0/b1 regs for nt=0..7
            {
                const uint32_t* p = As + b_base + (wn * 2 + ks) * 512;
                *(uint4*)&b0[0] = *(const uint4*)(p);          // h=0,q=0
                *(uint4*)&b0[4] = *(const uint4*)(p + 32);     // h=0,q=1
                *(uint4*)&b1[0] = *(const uint4*)(p + 64);     // h=1,q=0
                *(uint4*)&b1[4] = *(const uint4*)(p + 96);     // h=1,q=1
            }
            #pragma unroll
            for (int mt = 0; mt < 4; mt++)
                #pragma unroll
                for (int nt = 0; nt < 8; nt++) {
                    uint32_t bb[2] = { b0[nt], b1[nt] };
                    mma_f16(acc[mt][nt], af[mt], bb);
                }
        }

        __syncthreads();   // reads of stage s done -> safe to overwrite
    }

    // ---- epilogue (row-major fp32 C; same D layout as before) ----
    #pragma unroll
    for (int mt = 0; mt < 4; mt++) {
        const int row0 = by * BM + wm * 64 + mt * 16 + g;
        #pragma unroll
        for (int nt = 0; nt < 8; nt++) {
            const int col = bx * BN + wn * 64 + nt * 8 + t * 2;
            *(float2*)(C + (size_t)row0 * N + col) =
                make_float2(acc[mt][nt][0], acc[mt][nt][1]);
            *(float2*)(C + (size_t)(row0 + 8) * N + col) =
                make_float2(acc[mt][nt][2], acc[mt][nt][3]);
        }
    }
}

// ---------------------------------------------------------------------------
// x -> gathered rows, fp16, A-fragment layout
// ---------------------------------------------------------------------------
__global__ __launch_bounds__(256)
void cvt_x_gather_kernel(const float* __restrict__ x, __half* __restrict__ xt,
                         const int* __restrict__ win)
{
    int i = blockIdx.x * 256 + threadIdx.x;       // S_TOK*320 threads
    int s  = i / (KDIM / 4);
    int c4 = (i % (KDIM / 4)) * 4;
    float4 v = *(const float4*)(x + (size_t)win[s] * KDIM + c4);
    xt[addrA16(s, c4 + 0)] = __float2half_rn(v.x);
    xt[addrA16(s, c4 + 1)] = __float2half_rn(v.y);
    xt[addrA16(s, c4 + 2)] = __float2half_rn(v.z);
    xt[addrA16(s, c4 + 3)] = __float2half_rn(v.w);
}

// ---------------------------------------------------------------------------
// W[K,N] fp32 row-major -> fp16 B-fragment layout
// ---------------------------------------------------------------------------
__global__ __launch_bounds__(256)
void cvt_w_frag_kernel(const float* __restrict__ W, __half* __restrict__ WF, int N)
{
    int i = blockIdx.x * 256 + threadIdx.x;       // KDIM*(N/4) threads
    int k  = i / (N / 4);
    int n4 = (i % (N / 4)) * 4;
    float4 v = *(const float4*)(W + (size_t)k * N + n4);
    WF[addrB16(k, n4 + 0)] = __float2half_rn(v.x);
    WF[addrB16(k, n4 + 1)] = __float2half_rn(v.y);
    WF[addrB16(k, n4 + 2)] = __float2half_rn(v.z);
    WF[addrB16(k, n4 + 3)] = __float2half_rn(v.w);
}

// ---------------------------------------------------------------------------
// Windowed attention, RoPE fused; scatters y (fp16) into A-frag layout,
// rows in ORIGINAL token order (feeds GEMM2 directly).
// ---------------------------------------------------------------------------
__global__ __launch_bounds__(256)
void attn_kernel(const float* __restrict__ qkv, __half* __restrict__ y,
                 const int* __restrict__ win,
                 const float* __restrict__ cosp, const float* __restrict__ sinp)
{
    const int b = blockIdx.x >> 4;
    const int h = blockIdx.x & 15;

    __shared__ float qs[BLK][D_HEAD + 1];
    __shared__ float ks[BLK][D_HEAD + 1];
    __shared__ float vs[BLK][D_HEAD + 1];
    __shared__ float att[BLK][BLK + 1];
    __shared__ int   toks[BLK];

    const int tid = threadIdx.x;
    if (tid < BLK) toks[tid] = win[b * BLK + tid];
    __syncthreads();

    for (int tdx = tid; tdx < BLK * D_HEAD; tdx += 256) {
        int i = tdx / D_HEAD, d = tdx % D_HEAD;
        size_t base = (size_t)(b * BLK + i) * C3 + (size_t)h * D_HEAD + d;
        float q = qkv[base];
        float k = qkv[base + C_DIM];
        float v = qkv[base + 2 * C_DIM];
        int tok = toks[i];
        float cv = cosp[(size_t)tok * D_HEAD + d];
        float sv = sinp[(size_t)tok * D_HEAD + d];
        qs[i][d] = q * cv + k * sv;
        ks[i][d] = k * cv - q * sv;
        vs[i][d] = v;
    }
    __syncthreads();

    {
        int i = tid >> 4, j = tid & 15;
        float sc = 0.f;
        #pragma unroll
        for (int d = 0; d < D_HEAD; d++) sc += qs[i][d] * ks[j][d];
        att[i][j] = sc * 0.11180339887498949f;   // 1/sqrt(80)
    }
    __syncthreads();

    if (tid < BLK) {
        float m = -1e30f;
        #pragma unroll
        for (int j = 0; j < BLK; j++) m = fmaxf(m, att[tid][j]);
        float sum = 0.f;
        #pragma unroll
        for (int j = 0; j < BLK; j++) {
            float e = __expf(att[tid][j] - m);
            att[tid][j] = e;
            sum += e;
        }
        float inv = 1.f / sum;
        #pragma unroll
        for (int j = 0; j < BLK; j++) att[tid][j] *= inv;
    }
    __syncthreads();

    for (int tdx = tid; tdx < BLK * D_HEAD; tdx += 256) {
        int i = tdx / D_HEAD, d = tdx % D_HEAD;
        float a = 0.f;
        #pragma unroll
        for (int j = 0; j < BLK; j++) a += att[i][j] * vs[j][d];
        y[addrA16(toks[i], h * D_HEAD + d)] = __float2half_rn(a);
    }
}

// ---------------------------------------------------------------------------
extern "C" void kernel_launch(void* const* d_in, const int* in_sizes, int n_in,
                              void* d_out, int out_size)
{
    const float* x     = (const float*)d_in[0];
    const float* cosp  = (const float*)d_in[1];
    const float* sinp  = (const float*)d_in[2];
    const float* Wqkv  = (const float*)d_in[3];
    const float* Wproj = (const float*)d_in[4];
    const int*   win   = (const int*)  d_in[5];
    float* out = (float*)d_out;

    float *qkv_ptr;
    __half *xt_ptr, *y_ptr, *wqkv_ptr, *wproj_ptr;
    cudaGetSymbolAddress((void**)&qkv_ptr,   g_qkv);
    cudaGetSymbolAddress((void**)&xt_ptr,    g_xt);
    cudaGetSymbolAddress((void**)&y_ptr,     g_y);
    cudaGetSymbolAddress((void**)&wqkv_ptr,  g_wqkvF);
    cudaGetSymbolAddress((void**)&wproj_ptr, g_wprojF);

    cudaFuncSetAttribute(mma_gemm_h,
        cudaFuncAttributeMaxDynamicSharedMemorySize, SMEM_BYTES);

    // 0) pre-permute inputs: x (gather + fp16 + A-frag), weights (fp16 + B-frag)
    cvt_x_gather_kernel<<<(S_TOK * (KDIM / 4)) / 256, 256>>>(x, xt_ptr, win);
    cvt_w_frag_kernel<<<(KDIM * (C3 / 4)) / 256, 256>>>(Wqkv, wqkv_ptr, C3);
    cvt_w_frag_kernel<<<(KDIM * (C_DIM / 4)) / 256, 256>>>(Wproj, wproj_ptr, C_DIM);

    // 1) QKV GEMM: g_qkv = g_xt @ W_qkv   (gather already applied)
    {
        dim3 grid(C3 / BN, S_TOK / BM);   // 30 x 128
        mma_gemm_h<<<grid, 128, SMEM_BYTES>>>(xt_ptr, wqkv_ptr, qkv_ptr, C3);
    }

    // 2) Windowed attention (RoPE fused) -> g_y (fp16 A-frag, original order)
    attn_kernel<<<NBLK * 16, 256>>>(qkv_ptr, y_ptr, win, cosp, sinp);

    // 3) Output projection: out = g_y @ W_proj
    {
        dim3 grid(C_DIM / BN, S_TOK / BM);  // 10 x 128
        mma_gemm_h<<<grid, 128, SMEM_BYTES>>>(y_ptr, wproj_ptr, out, C_DIM);
    }
}

// round 13
// speedup vs baseline: 1.8660x; 1.0659x over previous
#include <cuda_runtime.h>
#include <cuda_fp16.h>
#include <stdint.h>

// Problem constants (fixed by dataset)
#define S_TOK   16384
#define C_DIM   1280
#define C3      3840
#define D_HEAD  80
#define BLK     16
#define NBLK    (S_TOK / BLK)   // 1024
#define KDIM    1280
#define KT16    (KDIM / 16)     // 80 k-tiles of 16

// Scratch (__device__ globals; no allocation allowed)
__device__ __align__(128) __half g_qkv[(size_t)S_TOK * C3];         // GEMM1 out (fp16)
__device__ __align__(128) __half g_xt [(size_t)S_TOK * KDIM];       // x gathered, fp16 A-frag
__device__ __align__(128) __half g_y  [(size_t)S_TOK * KDIM];       // attn out, fp16 A-frag
__device__ __align__(128) __half g_wqkvF [(size_t)C3   * KDIM];     // W_qkv  fp16 B-frag
__device__ __align__(128) __half g_wprojF[(size_t)C_DIM * KDIM];    // W_proj fp16 B-frag

// ---------------------------------------------------------------------------
// fp16 A-fragment layout for mma.m16n8k16 (element index in __half units)
__device__ __forceinline__ size_t addrA16(int m, int k) {
    int l = (m & 7) * 4 + ((k >> 1) & 3);
    int r = ((m >> 3) & 1) + ((k >> 3) & 1) * 2;
    return ((size_t)((m >> 4) * KT16 + (k >> 4)) << 8) + l * 8 + r * 2 + (k & 1);
}
// fp16 B-fragment layout (weights K x N): block (16k x 64n) = 1024 halfs
__device__ __forceinline__ size_t addrB16(int k, int n) {
    int kk = k & 15, nn = n & 63;
    int t = (kk >> 1) & 3, h = (kk >> 3) & 1, e = kk & 1;
    int g = (nn & 7) ^ (kk & 6);
    int q = (nn >> 5) & 1, c = (nn >> 3) & 3;
    return (size_t)((n >> 6) * KT16 + (k >> 4)) * 1024
         + (size_t)((((t * 2 + h) * 2 + q) * 8 + g) * 8 + c * 2 + e);
}
__device__ __forceinline__ uint32_t smem_u32(const void* p) {
    uint32_t a;
    asm("{ .reg .u64 t; cvta.to.shared.u64 t, %1; cvt.u32.u64 %0, t; }" : "=r"(a) : "l"(p));
    return a;
}
__device__ __forceinline__ void cpa16(uint32_t dst, const void* src) {
    asm volatile("cp.async.cg.shared.global [%0], [%1], 16;" :: "r"(dst), "l"(src) : "memory");
}
__device__ __forceinline__ void cpa_commit() {
    asm volatile("cp.async.commit_group;" ::: "memory");
}
__device__ __forceinline__ void cpa_wait1() {
    asm volatile("cp.async.wait_group 1;" ::: "memory");
}
__device__ __forceinline__ void mma_f16(float* d, const uint32_t* a, const uint32_t* b) {
    asm volatile(
        "mma.sync.aligned.m16n8k16.row.col.f32.f16.f16.f32 "
        "{%0,%1,%2,%3}, {%4,%5,%6,%7}, {%8,%9}, {%0,%1,%2,%3};"
        : "+f"(d[0]), "+f"(d[1]), "+f"(d[2]), "+f"(d[3])
        : "r"(a[0]), "r"(a[1]), "r"(a[2]), "r"(a[3]),
          "r"(b[0]), "r"(b[1]));
}

// ---------------------------------------------------------------------------
// FP16 mma.sync GEMM, fragment-native smem (all frag loads = LDS.128).
// CTA 128x128, BK=64 (4 k16 steps), 128 thr (4 warps 2x2), warp tile 64x64.
// 3-stage cp.async pipeline (32KB/stage), 1 wait+2 sync per BK=64, 2 CTAs/SM.
// HOUT: C written as fp16 (half2); else fp32.
// ---------------------------------------------------------------------------
#define BM 128
#define BN 128
#define BK 64
#define A_STAGE_W 4096                   // words (16KB)
#define B_STAGE_W 4096                   // words (16KB)
#define ST_W (A_STAGE_W + B_STAGE_W)     // 8192 words / stage
#define NSTAGE 3
#define SMEM_BYTES (NSTAGE * ST_W * 4)   // 98304

template<bool HOUT>
__global__ __launch_bounds__(128, 2)
void mma_gemm_h(const __half* __restrict__ A, const __half* __restrict__ B,
                void* __restrict__ Cv, int N)
{
    extern __shared__ char smem[];
    const uint32_t sb = smem_u32(smem);
    uint32_t* smw = (uint32_t*)smem;

    const int tid  = threadIdx.x;
    const int bx   = blockIdx.x, by = blockIdx.y;
    const int warp = tid >> 5, lane = tid & 31;
    const int wm   = warp >> 1, wn = warp & 1;   // 2x2 warp grid
    const int g    = lane >> 2, t = lane & 3;

    // ---- producer mapping: 16 cpa16 / thread / stage ----
    // A: positions p = tid + 128*j (j=0..7); ca=p>>5 (0..31): rg=ca>>2, jk=ca&3
    const __half* Asrc[8];
    uint32_t a_dst[8];
    #pragma unroll
    for (int j = 0; j < 8; j++) {
        int p  = tid + 128 * j;
        int ca = p >> 5;
        int rg = ca >> 2, jk = ca & 3;
        Asrc[j] = A + ((size_t)(by * 8 + rg) * KT16 + jk) * 256 + (p & 31) * 8;
        a_dst[j] = (uint32_t)p * 16;
    }
    // B: chunks j=0..7 (2048B each): ngl=j>>2, jk=j&3
    const __half* Bsrc[8];
    uint32_t b_dst[8];
    #pragma unroll
    for (int j = 0; j < 8; j++) {
        int ngl = j >> 2, jk = j & 3;
        Bsrc[j] = B + ((size_t)(bx * 2 + ngl) * KT16 + jk) * 1024 + tid * 8;
        b_dst[j] = (uint32_t)(A_STAGE_W * 4) + (uint32_t)(j * 2048 + tid * 16);
    }
    // per-iter gmem advance: A +1024 halfs (4 k-tiles), B +4096 halfs

    // ---- consumer fragment bases (word offsets within a stage) ----
    const uint32_t a_base = (uint32_t)(lane * 4);
    const int gs = g ^ (2 * t);
    const uint32_t b_base = (uint32_t)(A_STAGE_W + t * 128 + gs * 4);

    float acc[4][8][4];
    #pragma unroll
    for (int mt = 0; mt < 4; mt++)
        #pragma unroll
        for (int nt = 0; nt < 8; nt++)
            #pragma unroll
            for (int i = 0; i < 4; i++) acc[mt][nt][i] = 0.f;

    const int NIT = KDIM / BK;   // 20

    // ---- prologue: issue stages 0,1 ----
    #pragma unroll
    for (int s = 0; s < NSTAGE - 1; s++) {
        const uint32_t so = sb + s * (ST_W * 4);
        #pragma unroll
        for (int j = 0; j < 8; j++)
            cpa16(so + a_dst[j], Asrc[j] + (size_t)s * 1024);
        #pragma unroll
        for (int j = 0; j < 8; j++)
            cpa16(so + b_dst[j], Bsrc[j] + (size_t)s * 4096);
        cpa_commit();
    }

    int stage = 0;
    for (int i = 0; i < NIT; i++) {
        cpa_wait1();          // group i complete -> stage i%3 ready
        __syncthreads();      // + reads of stage (i-1)%3 finished

        if (i + NSTAGE - 1 < NIT) {
            int s2 = stage + (NSTAGE - 1);
            if (s2 >= NSTAGE) s2 -= NSTAGE;
            const uint32_t so = sb + s2 * (ST_W * 4);
            const size_t ko = (size_t)(i + NSTAGE - 1);
            #pragma unroll
            for (int j = 0; j < 8; j++)
                cpa16(so + a_dst[j], Asrc[j] + ko * 1024);
            #pragma unroll
            for (int j = 0; j < 8; j++)
                cpa16(so + b_dst[j], Bsrc[j] + ko * 4096);
        }
        cpa_commit();

        // ---- compute: 4 k16 steps ----
        const uint32_t* As = smw + stage * ST_W;
        #pragma unroll
        for (int ks = 0; ks < 4; ks++) {
            uint32_t af[4][4];
            #pragma unroll
            for (int mt = 0; mt < 4; mt++)
                *(uint4*)af[mt] = *(const uint4*)
                    (As + ((wm * 4 + mt) * 4 + ks) * 128 + a_base);
            uint32_t b0[8], b1[8];
            {
                const uint32_t* p = As + b_base + (wn * 4 + ks) * 512;
                *(uint4*)&b0[0] = *(const uint4*)(p);          // h=0,q=0
                *(uint4*)&b0[4] = *(const uint4*)(p + 32);     // h=0,q=1
                *(uint4*)&b1[0] = *(const uint4*)(p + 64);     // h=1,q=0
                *(uint4*)&b1[4] = *(const uint4*)(p + 96);     // h=1,q=1
            }
            #pragma unroll
            for (int mt = 0; mt < 4; mt++)
                #pragma unroll
                for (int nt = 0; nt < 8; nt++) {
                    uint32_t bb[2] = { b0[nt], b1[nt] };
                    mma_f16(acc[mt][nt], af[mt], bb);
                }
        }

        stage = (stage + 1 == NSTAGE) ? 0 : stage + 1;
        __syncthreads();   // reads of this stage done -> safe overwrite
    }

    // ---- epilogue ----
    #pragma unroll
    for (int mt = 0; mt < 4; mt++) {
        const int row0 = by * BM + wm * 64 + mt * 16 + g;
        #pragma unroll
        for (int nt = 0; nt < 8; nt++) {
            const int col = bx * BN + wn * 64 + nt * 8 + t * 2;
            if (HOUT) {
                __half* C = (__half*)Cv;
                *(__half2*)(C + (size_t)row0 * N + col) =
                    __floats2half2_rn(acc[mt][nt][0], acc[mt][nt][1]);
                *(__half2*)(C + (size_t)(row0 + 8) * N + col) =
                    __floats2half2_rn(acc[mt][nt][2], acc[mt][nt][3]);
            } else {
                float* C = (float*)Cv;
                *(float2*)(C + (size_t)row0 * N + col) =
                    make_float2(acc[mt][nt][0], acc[mt][nt][1]);
                *(float2*)(C + (size_t)(row0 + 8) * N + col) =
                    make_float2(acc[mt][nt][2], acc[mt][nt][3]);
            }
        }
    }
}

// ---------------------------------------------------------------------------
// x -> gathered rows, fp16, A-fragment layout (half2 stores)
// ---------------------------------------------------------------------------
__global__ __launch_bounds__(256)
void cvt_x_gather_kernel(const float* __restrict__ x, __half* __restrict__ xt,
                         const int* __restrict__ win)
{
    int i = blockIdx.x * 256 + threadIdx.x;       // S_TOK*320 threads
    int s  = i / (KDIM / 4);
    int c4 = (i % (KDIM / 4)) * 4;
    float4 v = *(const float4*)(x + (size_t)win[s] * KDIM + c4);
    size_t a0 = addrA16(s, c4);                   // (k,k+1) adjacent; (k+2) at +8
    *(__half2*)(xt + a0)     = __floats2half2_rn(v.x, v.y);
    *(__half2*)(xt + a0 + 8) = __floats2half2_rn(v.z, v.w);
}

// ---------------------------------------------------------------------------
// W[K,N] fp32 row-major -> fp16 B-fragment layout
// ---------------------------------------------------------------------------
__global__ __launch_bounds__(256)
void cvt_w_frag_kernel(const float* __restrict__ W, __half* __restrict__ WF, int N)
{
    int i = blockIdx.x * 256 + threadIdx.x;       // KDIM*(N/4) threads
    int k  = i / (N / 4);
    int n4 = (i % (N / 4)) * 4;
    float4 v = *(const float4*)(W + (size_t)k * N + n4);
    WF[addrB16(k, n4 + 0)] = __float2half_rn(v.x);
    WF[addrB16(k, n4 + 1)] = __float2half_rn(v.y);
    WF[addrB16(k, n4 + 2)] = __float2half_rn(v.z);
    WF[addrB16(k, n4 + 3)] = __float2half_rn(v.w);
}

// ---------------------------------------------------------------------------
// Windowed attention, RoPE fused; reads fp16 qkv, scatters y (fp16) into
// A-frag layout, rows in ORIGINAL token order (feeds GEMM2 directly).
// ---------------------------------------------------------------------------
__global__ __launch_bounds__(256)
void attn_kernel(const __half* __restrict__ qkv, __half* __restrict__ y,
                 const int* __restrict__ win,
                 const float* __restrict__ cosp, const float* __restrict__ sinp)
{
    const int b = blockIdx.x >> 4;
    const int h = blockIdx.x & 15;

    __shared__ float qs[BLK][D_HEAD + 1];
    __shared__ float ks[BLK][D_HEAD + 1];
    __shared__ float vs[BLK][D_HEAD + 1];
    __shared__ float att[BLK][BLK + 1];
    __shared__ int   toks[BLK];

    const int tid = threadIdx.x;
    if (tid < BLK) toks[tid] = win[b * BLK + tid];
    __syncthreads();

    for (int tdx = tid; tdx < BLK * D_HEAD; tdx += 256) {
        int i = tdx / D_HEAD, d = tdx % D_HEAD;
        size_t base = (size_t)(b * BLK + i) * C3 + (size_t)h * D_HEAD + d;
        float q = __half2float(qkv[base]);
        float k = __half2float(qkv[base + C_DIM]);
        float v = __half2float(qkv[base + 2 * C_DIM]);
        int tok = toks[i];
        float cv = cosp[(size_t)tok * D_HEAD + d];
        float sv = sinp[(size_t)tok * D_HEAD + d];
        qs[i][d] = q * cv + k * sv;
        ks[i][d] = k * cv - q * sv;
        vs[i][d] = v;
    }
    __syncthreads();

    {
        int i = tid >> 4, j = tid & 15;
        float sc = 0.f;
        #pragma unroll
        for (int d = 0; d < D_HEAD; d++) sc += qs[i][d] * ks[j][d];
        att[i][j] = sc * 0.11180339887498949f;   // 1/sqrt(80)
    }
    __syncthreads();

    if (tid < BLK) {
        float m = -1e30f;
        #pragma unroll
        for (int j = 0; j < BLK; j++) m = fmaxf(m, att[tid][j]);
        float sum = 0.f;
        #pragma unroll
        for (int j = 0; j < BLK; j++) {
            float e = __expf(att[tid][j] - m);
            att[tid][j] = e;
            sum += e;
        }
        float inv = 1.f / sum;
        #pragma unroll
        for (int j = 0; j < BLK; j++) att[tid][j] *= inv;
    }
    __syncthreads();

    for (int tdx = tid; tdx < BLK * D_HEAD; tdx += 256) {
        int i = tdx / D_HEAD, d = tdx % D_HEAD;
        float a = 0.f;
        #pragma unroll
        for (int j = 0; j < BLK; j++) a += att[i][j] * vs[j][d];
        y[addrA16(toks[i], h * D_HEAD + d)] = __float2half_rn(a);
    }
}

// ---------------------------------------------------------------------------
extern "C" void kernel_launch(void* const* d_in, const int* in_sizes, int n_in,
                              void* d_out, int out_size)
{
    const float* x     = (const float*)d_in[0];
    const float* cosp  = (const float*)d_in[1];
    const float* sinp  = (const float*)d_in[2];
    const float* Wqkv  = (const float*)d_in[3];
    const float* Wproj = (const float*)d_in[4];
    const int*   win   = (const int*)  d_in[5];
    float* out = (float*)d_out;

    __half *qkv_ptr, *xt_ptr, *y_ptr, *wqkv_ptr, *wproj_ptr;
    cudaGetSymbolAddress((void**)&qkv_ptr,   g_qkv);
    cudaGetSymbolAddress((void**)&xt_ptr,    g_xt);
    cudaGetSymbolAddress((void**)&y_ptr,     g_y);
    cudaGetSymbolAddress((void**)&wqkv_ptr,  g_wqkvF);
    cudaGetSymbolAddress((void**)&wproj_ptr, g_wprojF);

    cudaFuncSetAttribute(mma_gemm_h<true>,
        cudaFuncAttributeMaxDynamicSharedMemorySize, SMEM_BYTES);
    cudaFuncSetAttribute(mma_gemm_h<false>,
        cudaFuncAttributeMaxDynamicSharedMemorySize, SMEM_BYTES);

    // 0) pre-permute inputs: x (gather + fp16 + A-frag), weights (fp16 + B-frag)
    cvt_x_gather_kernel<<<(S_TOK * (KDIM / 4)) / 256, 256>>>(x, xt_ptr, win);
    cvt_w_frag_kernel<<<(KDIM * (C3 / 4)) / 256, 256>>>(Wqkv, wqkv_ptr, C3);
    cvt_w_frag_kernel<<<(KDIM * (C_DIM / 4)) / 256, 256>>>(Wproj, wproj_ptr, C_DIM);

    // 1) QKV GEMM: g_qkv(fp16) = g_xt @ W_qkv
    {
        dim3 grid(C3 / BN, S_TOK / BM);   // 30 x 128
        mma_gemm_h<true><<<grid, 128, SMEM_BYTES>>>(xt_ptr, wqkv_ptr, qkv_ptr, C3);
    }

    // 2) Windowed attention (RoPE fused) -> g_y (fp16 A-frag, original order)
    attn_kernel<<<NBLK * 16, 256>>>(qkv_ptr, y_ptr, win, cosp, sinp);

    // 3) Output projection: out(fp32) = g_y @ W_proj
    {
        dim3 grid(C_DIM / BN, S_TOK / BM);  // 10 x 128
        mma_gemm_h<false><<<grid, 128, SMEM_BYTES>>>(y_ptr, wproj_ptr, out, C_DIM);
    }
}

// round 14
// speedup vs baseline: 1.8738x; 1.0042x over previous
#include <cuda_runtime.h>
#include <cuda_fp16.h>
#include <stdint.h>

// Problem constants (fixed by dataset)
#define S_TOK   16384
#define C_DIM   1280
#define C3      3840
#define D_HEAD  80
#define BLK     16
#define NBLK    (S_TOK / BLK)   // 1024
#define KDIM    1280
#define KT16    (KDIM / 16)     // 80

// Scratch (__device__ globals; no allocation allowed)
__device__ __align__(128) __half g_qkv[(size_t)S_TOK * C3];         // GEMM1 out (fp16, window order)
__device__ __align__(128) __half g_xt [(size_t)S_TOK * KDIM];       // x gathered, fp16 A-frag
__device__ __align__(128) __half g_y  [(size_t)S_TOK * KDIM];       // attn out, fp16 A-frag, WINDOW order
__device__ __align__(128) __half g_wqkvF [(size_t)C3   * KDIM];     // W_qkv  fp16 B-frag
__device__ __align__(128) __half g_wprojF[(size_t)C_DIM * KDIM];    // W_proj fp16 B-frag

// ---------------------------------------------------------------------------
__device__ __forceinline__ uint32_t smem_u32(const void* p) {
    uint32_t a;
    asm("{ .reg .u64 t; cvta.to.shared.u64 t, %1; cvt.u32.u64 %0, t; }" : "=r"(a) : "l"(p));
    return a;
}
__device__ __forceinline__ void cpa16(uint32_t dst, const void* src) {
    asm volatile("cp.async.cg.shared.global [%0], [%1], 16;" :: "r"(dst), "l"(src) : "memory");
}
__device__ __forceinline__ void cpa_commit() {
    asm volatile("cp.async.commit_group;" ::: "memory");
}
__device__ __forceinline__ void cpa_wait1() {
    asm volatile("cp.async.wait_group 1;" ::: "memory");
}
__device__ __forceinline__ void mma_f16(float* d, const uint32_t* a, const uint32_t* b) {
    asm volatile(
        "mma.sync.aligned.m16n8k16.row.col.f32.f16.f16.f32 "
        "{%0,%1,%2,%3}, {%4,%5,%6,%7}, {%8,%9}, {%0,%1,%2,%3};"
        : "+f"(d[0]), "+f"(d[1]), "+f"(d[2]), "+f"(d[3])
        : "r"(a[0]), "r"(a[1]), "r"(a[2]), "r"(a[3]),
          "r"(b[0]), "r"(b[1]));
}

// ---------------------------------------------------------------------------
// FP16 mma.sync GEMM (R13 structure): CTA 128x128, BK=64, 128 thr, warp 64x64,
// 3-stage cp.async, 2 CTAs/SM. Frag-native gmem layouts.
// HOUT: fp16 C.  SCAT: epilogue row m writes to C row win[m] (inverse perm).
// ---------------------------------------------------------------------------
#define BM 128
#define BN 128
#define BK 64
#define A_STAGE_W 4096
#define B_STAGE_W 4096
#define ST_W (A_STAGE_W + B_STAGE_W)     // 8192 words / stage
#define NSTAGE 3
#define SMEM_BYTES (NSTAGE * ST_W * 4)   // 98304

template<bool HOUT, bool SCAT>
__global__ __launch_bounds__(128, 2)
void mma_gemm_h(const __half* __restrict__ A, const __half* __restrict__ B,
                void* __restrict__ Cv, const int* __restrict__ win, int N)
{
    extern __shared__ char smem[];
    const uint32_t sb = smem_u32(smem);
    uint32_t* smw = (uint32_t*)smem;

    const int tid  = threadIdx.x;
    const int bx   = blockIdx.x, by = blockIdx.y;
    const int warp = tid >> 5, lane = tid & 31;
    const int wm   = warp >> 1, wn = warp & 1;
    const int g    = lane >> 2, t = lane & 3;

    // ---- producer mapping: 16 cpa16 / thread / stage ----
    const __half* Asrc[8];
    uint32_t a_dst[8];
    #pragma unroll
    for (int j = 0; j < 8; j++) {
        int p  = tid + 128 * j;
        int ca = p >> 5;
        int rg = ca >> 2, jk = ca & 3;
        Asrc[j] = A + ((size_t)(by * 8 + rg) * KT16 + jk) * 256 + (p & 31) * 8;
        a_dst[j] = (uint32_t)p * 16;
    }
    const __half* Bsrc[8];
    uint32_t b_dst[8];
    #pragma unroll
    for (int j = 0; j < 8; j++) {
        int ngl = j >> 2, jk = j & 3;
        Bsrc[j] = B + ((size_t)(bx * 2 + ngl) * KT16 + jk) * 1024 + tid * 8;
        b_dst[j] = (uint32_t)(A_STAGE_W * 4) + (uint32_t)(j * 2048 + tid * 16);
    }

    const uint32_t a_base = (uint32_t)(lane * 4);
    const int gs = g ^ (2 * t);
    const uint32_t b_base = (uint32_t)(A_STAGE_W + t * 128 + gs * 4);

    float acc[4][8][4];
    #pragma unroll
    for (int mt = 0; mt < 4; mt++)
        #pragma unroll
        for (int nt = 0; nt < 8; nt++)
            #pragma unroll
            for (int i = 0; i < 4; i++) acc[mt][nt][i] = 0.f;

    const int NIT = KDIM / BK;   // 20

    #pragma unroll
    for (int s = 0; s < NSTAGE - 1; s++) {
        const uint32_t so = sb + s * (ST_W * 4);
        #pragma unroll
        for (int j = 0; j < 8; j++)
            cpa16(so + a_dst[j], Asrc[j] + (size_t)s * 1024);
        #pragma unroll
        for (int j = 0; j < 8; j++)
            cpa16(so + b_dst[j], Bsrc[j] + (size_t)s * 4096);
        cpa_commit();
    }

    int stage = 0;
    for (int i = 0; i < NIT; i++) {
        cpa_wait1();
        __syncthreads();

        if (i + NSTAGE - 1 < NIT) {
            int s2 = stage + (NSTAGE - 1);
            if (s2 >= NSTAGE) s2 -= NSTAGE;
            const uint32_t so = sb + s2 * (ST_W * 4);
            const size_t ko = (size_t)(i + NSTAGE - 1);
            #pragma unroll
            for (int j = 0; j < 8; j++)
                cpa16(so + a_dst[j], Asrc[j] + ko * 1024);
            #pragma unroll
            for (int j = 0; j < 8; j++)
                cpa16(so + b_dst[j], Bsrc[j] + ko * 4096);
        }
        cpa_commit();

        const uint32_t* As = smw + stage * ST_W;
        #pragma unroll
        for (int ks = 0; ks < 4; ks++) {
            uint32_t af[4][4];
            #pragma unroll
            for (int mt = 0; mt < 4; mt++)
                *(uint4*)af[mt] = *(const uint4*)
                    (As + ((wm * 4 + mt) * 4 + ks) * 128 + a_base);
            uint32_t b0[8], b1[8];
            {
                const uint32_t* p = As + b_base + (wn * 4 + ks) * 512;
                *(uint4*)&b0[0] = *(const uint4*)(p);
                *(uint4*)&b0[4] = *(const uint4*)(p + 32);
                *(uint4*)&b1[0] = *(const uint4*)(p + 64);
                *(uint4*)&b1[4] = *(const uint4*)(p + 96);
            }
            #pragma unroll
            for (int mt = 0; mt < 4; mt++)
                #pragma unroll
                for (int nt = 0; nt < 8; nt++) {
                    uint32_t bb[2] = { b0[nt], b1[nt] };
                    mma_f16(acc[mt][nt], af[mt], bb);
                }
        }

        stage = (stage + 1 == NSTAGE) ? 0 : stage + 1;
        __syncthreads();
    }

    // ---- epilogue (optional inverse-permutation row scatter) ----
    #pragma unroll
    for (int mt = 0; mt < 4; mt++) {
        const int m0 = by * BM + wm * 64 + mt * 16 + g;
        int r0 = SCAT ? win[m0]     : m0;
        int r1 = SCAT ? win[m0 + 8] : m0 + 8;
        #pragma unroll
        for (int nt = 0; nt < 8; nt++) {
            const int col = bx * BN + wn * 64 + nt * 8 + t * 2;
            if (HOUT) {
                __half* C = (__half*)Cv;
                *(__half2*)(C + (size_t)r0 * N + col) =
                    __floats2half2_rn(acc[mt][nt][0], acc[mt][nt][1]);
                *(__half2*)(C + (size_t)r1 * N + col) =
                    __floats2half2_rn(acc[mt][nt][2], acc[mt][nt][3]);
            } else {
                float* C = (float*)Cv;
                *(float2*)(C + (size_t)r0 * N + col) =
                    make_float2(acc[mt][nt][0], acc[mt][nt][1]);
                *(float2*)(C + (size_t)r1 * N + col) =
                    make_float2(acc[mt][nt][2], acc[mt][nt][3]);
            }
        }
    }
}

// ---------------------------------------------------------------------------
// x -> gathered rows, fp16, A-frag layout. One CTA per 16-row m-tile;
// smem-staged so ALL gmem writes are coalesced uint4.
// ---------------------------------------------------------------------------
__global__ __launch_bounds__(256)
void cvt_x_gather_kernel(const float* __restrict__ x, __half* __restrict__ xt,
                         const int* __restrict__ win)
{
    __shared__ uint32_t st[KT16 * 128];   // 10240 words = 40KB (one m-tile)
    const int mt  = blockIdx.x;           // 0..1023
    const int tid = threadIdx.x;
    const int i   = tid >> 4;             // row within tile (0..15)
    const float* src = x + (size_t)win[mt * 16 + i] * KDIM;

    #pragma unroll
    for (int j = 0; j < 20; j++) {
        int c4 = ((tid & 15) + 16 * j) * 4;
        float4 v = *(const float4*)(src + c4);
        int kt = c4 >> 4;
        int l  = (i & 7) * 4 + ((c4 >> 1) & 3);
        int r  = (i >> 3) + ((c4 >> 3) & 1) * 2;
        int off = kt * 128 + l * 4 + r;
        __half2 h0 = __floats2half2_rn(v.x, v.y);
        __half2 h1 = __floats2half2_rn(v.z, v.w);
        st[off]     = *(uint32_t*)&h0;
        st[off + 4] = *(uint32_t*)&h1;
    }
    __syncthreads();

    uint4* dst = (uint4*)(xt + (size_t)mt * KT16 * 256);
    const uint4* s4 = (const uint4*)st;
    #pragma unroll
    for (int j = 0; j < 10; j++)
        dst[tid + 256 * j] = s4[tid + 256 * j];
}

// ---------------------------------------------------------------------------
// W[K,N] fp32 -> fp16 B-frag layout. CTA per (64-col group, 4 ktiles);
// smem-staged, coalesced uint4 writes.
// ---------------------------------------------------------------------------
__global__ __launch_bounds__(256)
void cvt_w_frag_kernel(const float* __restrict__ W, __half* __restrict__ WF, int N)
{
    __shared__ __half st[4096];           // 8KB: 4 ktile-blocks x 1024 halfs
    const int ngl = blockIdx.x;           // N/64
    const int kb  = blockIdx.y;           // KT16/4 = 20
    const int tid = threadIdx.x;

    #pragma unroll
    for (int j = 0; j < 4; j++) {
        int idx  = tid + 256 * j;         // 0..1023
        int krow = idx >> 4;              // 0..63
        int nc   = (idx & 15) * 4;        // 0..60
        int k = kb * 64 + krow;
        float4 v = *(const float4*)(W + (size_t)k * N + ngl * 64 + nc);
        int kk = k & 15, ktl = (k >> 4) & 3;
        int tt = (kk >> 1) & 3, hh = (kk >> 3) & 1, e = kk & 1;
        float vals[4] = { v.x, v.y, v.z, v.w };
        #pragma unroll
        for (int q2 = 0; q2 < 4; q2++) {
            int nn = nc + q2;
            int gg = (nn & 7) ^ (kk & 6);
            int qq = (nn >> 5) & 1, cc = (nn >> 3) & 3;
            int hoff = ktl * 1024 + ((((tt * 2 + hh) * 2 + qq) * 8 + gg) * 8 + cc * 2 + e);
            st[hoff] = __float2half_rn(vals[q2]);
        }
    }
    __syncthreads();

    uint4* dst = (uint4*)(WF + ((size_t)ngl * KT16 + kb * 4) * 1024);
    const uint4* s4 = (const uint4*)st;
    dst[tid]       = s4[tid];
    dst[tid + 256] = s4[tid + 256];
}

// ---------------------------------------------------------------------------
// Windowed attention, RoPE fused. Reads fp16 qkv (window order); writes g_y
// in WINDOW order (block b = m-tile b), coalesced uint32 frag writes.
// ---------------------------------------------------------------------------
__global__ __launch_bounds__(256)
void attn_kernel(const __half* __restrict__ qkv, __half* __restrict__ y,
                 const int* __restrict__ win,
                 const float* __restrict__ cosp, const float* __restrict__ sinp)
{
    const int b = blockIdx.x >> 4;
    const int h = blockIdx.x & 15;

    __shared__ float qs[BLK][D_HEAD + 1];
    __shared__ float ks[BLK][D_HEAD + 1];
    __shared__ float vs[BLK][D_HEAD + 1];
    __shared__ float att[BLK][BLK + 1];
    __shared__ float os[BLK][D_HEAD + 2];
    __shared__ int   toks[BLK];

    const int tid = threadIdx.x;
    if (tid < BLK) toks[tid] = win[b * BLK + tid];
    __syncthreads();

    for (int tdx = tid; tdx < BLK * D_HEAD; tdx += 256) {
        int i = tdx / D_HEAD, d = tdx % D_HEAD;
        size_t base = (size_t)(b * BLK + i) * C3 + (size_t)h * D_HEAD + d;
        float q = __half2float(qkv[base]);
        float k = __half2float(qkv[base + C_DIM]);
        float v = __half2float(qkv[base + 2 * C_DIM]);
        int tok = toks[i];
        float cv = cosp[(size_t)tok * D_HEAD + d];
        float sv = sinp[(size_t)tok * D_HEAD + d];
        qs[i][d] = q * cv + k * sv;
        ks[i][d] = k * cv - q * sv;
        vs[i][d] = v;
    }
    __syncthreads();

    {
        int i = tid >> 4, j = tid & 15;
        float sc = 0.f;
        #pragma unroll
        for (int d = 0; d < D_HEAD; d++) sc += qs[i][d] * ks[j][d];
        att[i][j] = sc * 0.11180339887498949f;   // 1/sqrt(80)
    }
    __syncthreads();

    if (tid < BLK) {
        float m = -1e30f;
        #pragma unroll
        for (int j = 0; j < BLK; j++) m = fmaxf(m, att[tid][j]);
        float sum = 0.f;
        #pragma unroll
        for (int j = 0; j < BLK; j++) {
            float e = __expf(att[tid][j] - m);
            att[tid][j] = e;
            sum += e;
        }
        float inv = 1.f / sum;
        #pragma unroll
        for (int j = 0; j < BLK; j++) att[tid][j] *= inv;
    }
    __syncthreads();

    for (int tdx = tid; tdx < BLK * D_HEAD; tdx += 256) {
        int i = tdx / D_HEAD, d = tdx % D_HEAD;
        float a = 0.f;
        #pragma unroll
        for (int j = 0; j < BLK; j++) a += att[i][j] * vs[j][d];
        os[i][d] = a;
    }
    __syncthreads();

    // coalesced frag-layout writes: 640 uint32 per CTA (5 ktiles x 128)
    for (int idx = tid; idx < 5 * 128; idx += 256) {
        int ktl = idx >> 7;              // local ktile 0..4
        int w   = idx & 127;             // uint32 slot within 512B block
        int l = w >> 2, r = w & 3;
        int i  = ((r & 1) << 3) | (l >> 2);
        int k0 = ((r >> 1) << 3) | ((l & 3) << 1);
        int d  = ktl * 16 + k0;
        __half2 v2 = __floats2half2_rn(os[i][d], os[i][d + 1]);
        *(__half2*)(y + ((size_t)b * KT16 + 5 * h + ktl) * 256 + (size_t)w * 2) = v2;
    }
}

// ---------------------------------------------------------------------------
extern "C" void kernel_launch(void* const* d_in, const int* in_sizes, int n_in,
                              void* d_out, int out_size)
{
    const float* x     = (const float*)d_in[0];
    const float* cosp  = (const float*)d_in[1];
    const float* sinp  = (const float*)d_in[2];
    const float* Wqkv  = (const float*)d_in[3];
    const float* Wproj = (const float*)d_in[4];
    const int*   win   = (const int*)  d_in[5];
    float* out = (float*)d_out;

    __half *qkv_ptr, *xt_ptr, *y_ptr, *wqkv_ptr, *wproj_ptr;
    cudaGetSymbolAddress((void**)&qkv_ptr,   g_qkv);
    cudaGetSymbolAddress((void**)&xt_ptr,    g_xt);
    cudaGetSymbolAddress((void**)&y_ptr,     g_y);
    cudaGetSymbolAddress((void**)&wqkv_ptr,  g_wqkvF);
    cudaGetSymbolAddress((void**)&wproj_ptr, g_wprojF);

    cudaFuncSetAttribute((const void*)mma_gemm_h<true, false>,
        cudaFuncAttributeMaxDynamicSharedMemorySize, SMEM_BYTES);
    cudaFuncSetAttribute((const void*)mma_gemm_h<false, true>,
        cudaFuncAttributeMaxDynamicSharedMemorySize, SMEM_BYTES);

    // 0) pre-permute inputs (all writes coalesced via smem staging)
    cvt_x_gather_kernel<<<NBLK, 256>>>(x, xt_ptr, win);
    cvt_w_frag_kernel<<<dim3(C3 / 64,   KT16 / 4), 256>>>(Wqkv,  wqkv_ptr,  C3);
    cvt_w_frag_kernel<<<dim3(C_DIM / 64, KT16 / 4), 256>>>(Wproj, wproj_ptr, C_DIM);

    // 1) QKV GEMM: g_qkv(fp16, window order) = g_xt @ W_qkv
    {
        dim3 grid(C3 / BN, S_TOK / BM);   // 30 x 128
        mma_gemm_h<true, false><<<grid, 128, SMEM_BYTES>>>(
            xt_ptr, wqkv_ptr, qkv_ptr, nullptr, C3);
    }

    // 2) Windowed attention (RoPE fused) -> g_y (fp16 A-frag, WINDOW order)
    attn_kernel<<<NBLK * 16, 256>>>(qkv_ptr, y_ptr, win, cosp, sinp);

    // 3) Output projection with inverse-permutation row scatter:
    //    out[win[m]] = g_y[m] @ W_proj
    {
        dim3 grid(C_DIM / BN, S_TOK / BM);  // 10 x 128
        mma_gemm_h<false, true><<<grid, 128, SMEM_BYTES>>>(
            y_ptr, wproj_ptr, out, win, C_DIM);
    }
}

// round 16
// speedup vs baseline: 1.8972x; 1.0125x over previous
#include <cuda_runtime.h>
#include <cuda_fp16.h>
#include <stdint.h>

// Problem constants (fixed by dataset)
#define S_TOK   16384
#define C_DIM   1280
#define C3      3840
#define D_HEAD  80
#define BLK     16
#define NBLK    (S_TOK / BLK)   // 1024
#define KDIM    1280
#define KT16    (KDIM / 16)     // 80

// Scratch (__device__ globals; no allocation allowed)
__device__ __align__(128) __half g_qkv[(size_t)S_TOK * C3];         // GEMM1 out (fp16, window order)
__device__ __align__(128) __half g_xt [(size_t)S_TOK * KDIM];       // x gathered, fp16 A-frag
__device__ __align__(128) __half g_y  [(size_t)S_TOK * KDIM];       // attn out, fp16 A-frag, WINDOW order
__device__ __align__(128) __half g_wqkvF [(size_t)C3   * KDIM];     // W_qkv  fp16 B-frag
__device__ __align__(128) __half g_wprojF[(size_t)C_DIM * KDIM];    // W_proj fp16 B-frag

// ---------------------------------------------------------------------------
__device__ __forceinline__ uint32_t smem_u32(const void* p) {
    uint32_t a;
    asm("{ .reg .u64 t; cvta.to.shared.u64 t, %1; cvt.u32.u64 %0, t; }" : "=r"(a) : "l"(p));
    return a;
}
__device__ __forceinline__ void cpa16(uint32_t dst, const void* src) {
    asm volatile("cp.async.cg.shared.global [%0], [%1], 16;" :: "r"(dst), "l"(src) : "memory");
}
__device__ __forceinline__ void cpa_commit() {
    asm volatile("cp.async.commit_group;" ::: "memory");
}
__device__ __forceinline__ void cpa_wait2() {
    asm volatile("cp.async.wait_group 2;" ::: "memory");
}
__device__ __forceinline__ void cpa_wait0() {
    asm volatile("cp.async.wait_group 0;" ::: "memory");
}
__device__ __forceinline__ void mma_f16(float* d, const uint32_t* a, const uint32_t* b) {
    asm volatile(
        "mma.sync.aligned.m16n8k16.row.col.f32.f16.f16.f32 "
        "{%0,%1,%2,%3}, {%4,%5,%6,%7}, {%8,%9}, {%0,%1,%2,%3};"
        : "+f"(d[0]), "+f"(d[1]), "+f"(d[2]), "+f"(d[3])
        : "r"(a[0]), "r"(a[1]), "r"(a[2]), "r"(a[3]),
          "r"(b[0]), "r"(b[1]));
}

// ---------------------------------------------------------------------------
// FP16 mma.sync GEMM: CTA 128x128, BK=32 (2 k16 steps), 128 thr (4 warps 2x2),
// warp tile 64x64. 4-stage cp.async pipeline, R9-proven single-sync order:
//   wait_group 2 -> __syncthreads -> issue(i+3) -> commit -> compute(i)
// 2 CTAs/SM. HOUT: fp16 C via smem-staged coalesced stores.
// SCAT: epilogue row m -> C row win[m] (inverse permutation).
// ---------------------------------------------------------------------------
#define BM 128
#define BN 128
#define BK 32
#define A_STAGE_W 2048                   // words (8KB)
#define B_STAGE_W 2048                   // words (8KB)
#define ST_W (A_STAGE_W + B_STAGE_W)     // 4096 words / stage
#define NSTAGE 4
#define SMEM_BYTES (NSTAGE * ST_W * 4)   // 65536
#define CSTG_STRIDE 68                   // epilogue staging row stride (words)

template<bool HOUT, bool SCAT>
__global__ __launch_bounds__(128, 2)
void mma_gemm_h(const __half* __restrict__ A, const __half* __restrict__ B,
                void* __restrict__ Cv, const int* __restrict__ win, int N)
{
    extern __shared__ char smem[];
    const uint32_t sb = smem_u32(smem);
    uint32_t* smw = (uint32_t*)smem;

    const int tid  = threadIdx.x;
    const int bx   = blockIdx.x, by = blockIdx.y;
    const int warp = tid >> 5, lane = tid & 31;
    const int wm   = warp >> 1, wn = warp & 1;
    const int g    = lane >> 2, t = lane & 3;

    // ---- producer mapping: 8 cpa16 / thread / stage (BK=32) ----
    const __half* Asrc[4];
    uint32_t a_dst[4];
    #pragma unroll
    for (int j = 0; j < 4; j++) {
        int p  = tid + 128 * j;
        int ca = p >> 5;                 // 0..15
        int rg = ca >> 1, jk = ca & 1;
        Asrc[j] = A + ((size_t)(by * 8 + rg) * KT16 + jk) * 256 + (p & 31) * 8;
        a_dst[j] = (uint32_t)p * 16;
    }
    const __half* Bsrc[4];
    uint32_t b_dst[4];
    #pragma unroll
    for (int j = 0; j < 4; j++) {
        int ngl = j >> 1, jk = j & 1;
        Bsrc[j] = B + ((size_t)(bx * 2 + ngl) * KT16 + jk) * 1024 + tid * 8;
        b_dst[j] = (uint32_t)(A_STAGE_W * 4) + (uint32_t)(j * 2048 + tid * 16);
    }
    // per-iter gmem advance: A +512 halfs (2 k-tiles), B +2048 halfs

    const uint32_t a_base = (uint32_t)(lane * 4);
    const int gs = g ^ (2 * t);
    const uint32_t b_base = (uint32_t)(A_STAGE_W + t * 128 + gs * 4);

    float acc[4][8][4];
    #pragma unroll
    for (int mt = 0; mt < 4; mt++)
        #pragma unroll
        for (int nt = 0; nt < 8; nt++)
            #pragma unroll
            for (int i = 0; i < 4; i++) acc[mt][nt][i] = 0.f;

    const int NIT = KDIM / BK;   // 40

    // ---- prologue: issue stages 0..2 ----
    #pragma unroll
    for (int s = 0; s < NSTAGE - 1; s++) {
        const uint32_t so = sb + s * (ST_W * 4);
        #pragma unroll
        for (int j = 0; j < 4; j++)
            cpa16(so + a_dst[j], Asrc[j] + (size_t)s * 512);
        #pragma unroll
        for (int j = 0; j < 4; j++)
            cpa16(so + b_dst[j], Bsrc[j] + (size_t)s * 2048);
        cpa_commit();
    }

    for (int i = 0; i < NIT; i++) {
        const int s = i & 3;
        cpa_wait2();          // group i complete -> stage i%4 landed (this thread)
        __syncthreads();      // publish all threads' copies + reads of (i-1)%4 done

        if (i + NSTAGE - 1 < NIT) {
            const int s3 = (i + NSTAGE - 1) & 3;     // == (i-1)&3
            const uint32_t so = sb + s3 * (ST_W * 4);
            const size_t ko = (size_t)(i + NSTAGE - 1);
            #pragma unroll
            for (int j = 0; j < 4; j++)
                cpa16(so + a_dst[j], Asrc[j] + ko * 512);
            #pragma unroll
            for (int j = 0; j < 4; j++)
                cpa16(so + b_dst[j], Bsrc[j] + ko * 2048);
        }
        cpa_commit();

        // ---- compute: 2 k16 steps ----
        const uint32_t* As = smw + s * ST_W;
        #pragma unroll
        for (int ks = 0; ks < 2; ks++) {
            uint32_t af[4][4];
            #pragma unroll
            for (int mt = 0; mt < 4; mt++)
                *(uint4*)af[mt] = *(const uint4*)
                    (As + ((wm * 4 + mt) * 2 + ks) * 128 + a_base);
            uint32_t b0[8], b1[8];
            {
                const uint32_t* p = As + b_base + (wn * 2 + ks) * 512;
                *(uint4*)&b0[0] = *(const uint4*)(p);
                *(uint4*)&b0[4] = *(const uint4*)(p + 32);
                *(uint4*)&b1[0] = *(const uint4*)(p + 64);
                *(uint4*)&b1[4] = *(const uint4*)(p + 96);
            }
            #pragma unroll
            for (int mt = 0; mt < 4; mt++)
                #pragma unroll
                for (int nt = 0; nt < 8; nt++) {
                    uint32_t bb[2] = { b0[nt], b1[nt] };
                    mma_f16(acc[mt][nt], af[mt], bb);
                }
        }
    }

    // ---- epilogue ----
    if (HOUT) {
        cpa_wait0();          // drain any trailing (empty) groups
        __syncthreads();      // pipeline smem now reusable
        __half* stg = (__half*)smem;
        #pragma unroll
        for (int mt = 0; mt < 4; mt++) {
            const int r0 = wm * 64 + mt * 16 + g;
            #pragma unroll
            for (int nt = 0; nt < 8; nt++) {
                const int col = wn * 64 + nt * 8 + t * 2;
                *(__half2*)(stg + (size_t)r0 * (CSTG_STRIDE * 2) + col) =
                    __floats2half2_rn(acc[mt][nt][0], acc[mt][nt][1]);
                *(__half2*)(stg + (size_t)(r0 + 8) * (CSTG_STRIDE * 2) + col) =
                    __floats2half2_rn(acc[mt][nt][2], acc[mt][nt][3]);
            }
        }
        __syncthreads();
        __half* C = (__half*)Cv;
        #pragma unroll
        for (int pass = 0; pass < 8; pass++) {
            int row = pass * 16 + (tid >> 3);
            const uint4* srow = (const uint4*)(smw + (size_t)row * CSTG_STRIDE);
            uint4 v0 = srow[tid & 7];
            uint4 v1 = srow[(tid & 7) + 8];
            int gr = SCAT ? win[by * BM + row] : by * BM + row;
            uint4* Crow = (uint4*)(C + (size_t)gr * N + bx * BN);
            Crow[tid & 7]       = v0;
            Crow[(tid & 7) + 8] = v1;
        }
    } else {
        #pragma unroll
        for (int mt = 0; mt < 4; mt++) {
            const int m0 = by * BM + wm * 64 + mt * 16 + g;
            int r0 = SCAT ? win[m0]     : m0;
            int r1 = SCAT ? win[m0 + 8] : m0 + 8;
            float* C = (float*)Cv;
            #pragma unroll
            for (int nt = 0; nt < 8; nt++) {
                const int col = bx * BN + wn * 64 + nt * 8 + t * 2;
                *(float2*)(C + (size_t)r0 * N + col) =
                    make_float2(acc[mt][nt][0], acc[mt][nt][1]);
                *(float2*)(C + (size_t)r1 * N + col) =
                    make_float2(acc[mt][nt][2], acc[mt][nt][3]);
            }
        }
    }
}

// ---------------------------------------------------------------------------
// x -> gathered rows, fp16, A-frag layout (smem-staged, coalesced writes)
// ---------------------------------------------------------------------------
__global__ __launch_bounds__(256)
void cvt_x_gather_kernel(const float* __restrict__ x, __half* __restrict__ xt,
                         const int* __restrict__ win)
{
    __shared__ uint32_t st[KT16 * 128];   // 40KB (one m-tile)
    const int mt  = blockIdx.x;           // 0..1023
    const int tid = threadIdx.x;
    const int i   = tid >> 4;             // row within tile (0..15)
    const float* src = x + (size_t)win[mt * 16 + i] * KDIM;

    #pragma unroll
    for (int j = 0; j < 20; j++) {
        int c4 = ((tid & 15) + 16 * j) * 4;
        float4 v = *(const float4*)(src + c4);
        int kt = c4 >> 4;
        int l  = (i & 7) * 4 + ((c4 >> 1) & 3);
        int r  = (i >> 3) + ((c4 >> 3) & 1) * 2;
        int off = kt * 128 + l * 4 + r;
        __half2 h0 = __floats2half2_rn(v.x, v.y);
        __half2 h1 = __floats2half2_rn(v.z, v.w);
        st[off]     = *(uint32_t*)&h0;
        st[off + 4] = *(uint32_t*)&h1;
    }
    __syncthreads();

    uint4* dst = (uint4*)(xt + (size_t)mt * KT16 * 256);
    const uint4* s4 = (const uint4*)st;
    #pragma unroll
    for (int j = 0; j < 10; j++)
        dst[tid + 256 * j] = s4[tid + 256 * j];
}

// ---------------------------------------------------------------------------
// W[K,N] fp32 -> fp16 B-frag layout (smem-staged, coalesced writes)
// ---------------------------------------------------------------------------
__global__ __launch_bounds__(256)
void cvt_w_frag_kernel(const float* __restrict__ W, __half* __restrict__ WF, int N)
{
    __shared__ __half st[4096];
    const int ngl = blockIdx.x;
    const int kb  = blockIdx.y;
    const int tid = threadIdx.x;

    #pragma unroll
    for (int j = 0; j < 4; j++) {
        int idx  = tid + 256 * j;
        int krow = idx >> 4;
        int nc   = (idx & 15) * 4;
        int k = kb * 64 + krow;
        float4 v = *(const float4*)(W + (size_t)k * N + ngl * 64 + nc);
        int kk = k & 15, ktl = (k >> 4) & 3;
        int tt = (kk >> 1) & 3, hh = (kk >> 3) & 1, e = kk & 1;
        float vals[4] = { v.x, v.y, v.z, v.w };
        #pragma unroll
        for (int q2 = 0; q2 < 4; q2++) {
            int nn = nc + q2;
            int gg = (nn & 7) ^ (kk & 6);
            int qq = (nn >> 5) & 1, cc = (nn >> 3) & 3;
            int hoff = ktl * 1024 + ((((tt * 2 + hh) * 2 + qq) * 8 + gg) * 8 + cc * 2 + e);
            st[hoff] = __float2half_rn(vals[q2]);
        }
    }
    __syncthreads();

    uint4* dst = (uint4*)(WF + ((size_t)ngl * KT16 + kb * 4) * 1024);
    const uint4* s4 = (const uint4*)st;
    dst[tid]       = s4[tid];
    dst[tid + 256] = s4[tid + 256];
}

// ---------------------------------------------------------------------------
// Windowed attention, RoPE fused. Reads fp16 qkv (window order); writes g_y
// in WINDOW order (block b = m-tile b), coalesced frag writes.
// ---------------------------------------------------------------------------
__global__ __launch_bounds__(256)
void attn_kernel(const __half* __restrict__ qkv, __half* __restrict__ y,
                 const int* __restrict__ win,
                 const float* __restrict__ cosp, const float* __restrict__ sinp)
{
    const int b = blockIdx.x >> 4;
    const int h = blockIdx.x & 15;

    __shared__ float qs[BLK][D_HEAD + 1];
    __shared__ float ks[BLK][D_HEAD + 1];
    __shared__ float vs[BLK][D_HEAD + 1];
    __shared__ float att[BLK][BLK + 1];
    __shared__ float os[BLK][D_HEAD + 2];
    __shared__ int   toks[BLK];

    const int tid = threadIdx.x;
    if (tid < BLK) toks[tid] = win[b * BLK + tid];
    __syncthreads();

    for (int tdx = tid; tdx < BLK * D_HEAD; tdx += 256) {
        int i = tdx / D_HEAD, d = tdx % D_HEAD;
        size_t base = (size_t)(b * BLK + i) * C3 + (size_t)h * D_HEAD + d;
        float q = __half2float(qkv[base]);
        float k = __half2float(qkv[base + C_DIM]);
        float v = __half2float(qkv[base + 2 * C_DIM]);
        int tok = toks[i];
        float cv = cosp[(size_t)tok * D_HEAD + d];
        float sv = sinp[(size_t)tok * D_HEAD + d];
        qs[i][d] = q * cv + k * sv;
        ks[i][d] = k * cv - q * sv;
        vs[i][d] = v;
    }
    __syncthreads();

    {
        int i = tid >> 4, j = tid & 15;
        float sc = 0.f;
        #pragma unroll
        for (int d = 0; d < D_HEAD; d++) sc += qs[i][d] * ks[j][d];
        att[i][j] = sc * 0.11180339887498949f;   // 1/sqrt(80)
    }
    __syncthreads();

    if (tid < BLK) {
        float m = -1e30f;
        #pragma unroll
        for (int j = 0; j < BLK; j++) m = fmaxf(m, att[tid][j]);
        float sum = 0.f;
        #pragma unroll
        for (int j = 0; j < BLK; j++) {
            float e = __expf(att[tid][j] - m);
            att[tid][j] = e;
            sum += e;
        }
        float inv = 1.f / sum;
        #pragma unroll
        for (int j = 0; j < BLK; j++) att[tid][j] *= inv;
    }
    __syncthreads();

    for (int tdx = tid; tdx < BLK * D_HEAD; tdx += 256) {
        int i = tdx / D_HEAD, d = tdx % D_HEAD;
        float a = 0.f;
        #pragma unroll
        for (int j = 0; j < BLK; j++) a += att[i][j] * vs[j][d];
        os[i][d] = a;
    }
    __syncthreads();

    for (int idx = tid; idx < 5 * 128; idx += 256) {
        int ktl = idx >> 7;
        int w   = idx & 127;
        int l = w >> 2, r = w & 3;
        int i  = ((r & 1) << 3) | (l >> 2);
        int k0 = ((r >> 1) << 3) | ((l & 3) << 1);
        int d  = ktl * 16 + k0;
        __half2 v2 = __floats2half2_rn(os[i][d], os[i][d + 1]);
        *(__half2*)(y + ((size_t)b * KT16 + 5 * h + ktl) * 256 + (size_t)w * 2) = v2;
    }
}

// ---------------------------------------------------------------------------
extern "C" void kernel_launch(void* const* d_in, const int* in_sizes, int n_in,
                              void* d_out, int out_size)
{
    const float* x     = (const float*)d_in[0];
    const float* cosp  = (const float*)d_in[1];
    const float* sinp  = (const float*)d_in[2];
    const float* Wqkv  = (const float*)d_in[3];
    const float* Wproj = (const float*)d_in[4];
    const int*   win   = (const int*)  d_in[5];
    float* out = (float*)d_out;

    __half *qkv_ptr, *xt_ptr, *y_ptr, *wqkv_ptr, *wproj_ptr;
    cudaGetSymbolAddress((void**)&qkv_ptr,   g_qkv);
    cudaGetSymbolAddress((void**)&xt_ptr,    g_xt);
    cudaGetSymbolAddress((void**)&y_ptr,     g_y);
    cudaGetSymbolAddress((void**)&wqkv_ptr,  g_wqkvF);
    cudaGetSymbolAddress((void**)&wproj_ptr, g_wprojF);

    cudaFuncSetAttribute((const void*)mma_gemm_h<true, false>,
        cudaFuncAttributeMaxDynamicSharedMemorySize, SMEM_BYTES);
    cudaFuncSetAttribute((const void*)mma_gemm_h<false, true>,
        cudaFuncAttributeMaxDynamicSharedMemorySize, SMEM_BYTES);

    // 0) pre-permute inputs
    cvt_x_gather_kernel<<<NBLK, 256>>>(x, xt_ptr, win);
    cvt_w_frag_kernel<<<dim3(C3 / 64,   KT16 / 4), 256>>>(Wqkv,  wqkv_ptr,  C3);
    cvt_w_frag_kernel<<<dim3(C_DIM / 64, KT16 / 4), 256>>>(Wproj, wproj_ptr, C_DIM);

    // 1) QKV GEMM: g_qkv(fp16, window order) = g_xt @ W_qkv
    {
        dim3 grid(C3 / BN, S_TOK / BM);   // 30 x 128
        mma_gemm_h<true, false><<<grid, 128, SMEM_BYTES>>>(
            xt_ptr, wqkv_ptr, qkv_ptr, nullptr, C3);
    }

    // 2) Windowed attention (RoPE fused) -> g_y (fp16 A-frag, WINDOW order)
    attn_kernel<<<NBLK * 16, 256>>>(qkv_ptr, y_ptr, win, cosp, sinp);

    // 3) Output projection with inverse-permutation row scatter:
    //    out[win[m]] = g_y[m] @ W_proj
    {
        dim3 grid(C_DIM / BN, S_TOK / BM);  // 10 x 128
        mma_gemm_h<false, true><<<grid, 128, SMEM_BYTES>>>(
            y_ptr, wproj_ptr, out, win, C_DIM);
    }
}

// round 17
// speedup vs baseline: 2.0620x; 1.0869x over previous
#include <cuda_runtime.h>
#include <cuda_fp16.h>
#include <stdint.h>

// Problem constants (fixed by dataset)
#define S_TOK   16384
#define C_DIM   1280
#define C3      3840
#define D_HEAD  80
#define BLK     16
#define NBLK    (S_TOK / BLK)   // 1024
#define KDIM    1280
#define KT16    (KDIM / 16)     // 80

// Scratch (__device__ globals; no allocation allowed)
__device__ __align__(128) __half g_qkv[(size_t)S_TOK * C3];         // GEMM1 out (fp16, window order)
__device__ __align__(128) __half g_xt [(size_t)S_TOK * KDIM];       // x gathered, fp16 A-frag
__device__ __align__(128) __half g_y  [(size_t)S_TOK * KDIM];       // attn out, fp16 A-frag, WINDOW order
__device__ __align__(128) __half g_wqkvF [(size_t)C3   * KDIM];     // W_qkv  fp16 B-frag
__device__ __align__(128) __half g_wprojF[(size_t)C_DIM * KDIM];    // W_proj fp16 B-frag

// ---------------------------------------------------------------------------
__device__ __forceinline__ uint32_t smem_u32(const void* p) {
    uint32_t a;
    asm("{ .reg .u64 t; cvta.to.shared.u64 t, %1; cvt.u32.u64 %0, t; }" : "=r"(a) : "l"(p));
    return a;
}
__device__ __forceinline__ void cpa16(uint32_t dst, const void* src) {
    asm volatile("cp.async.cg.shared.global [%0], [%1], 16;" :: "r"(dst), "l"(src) : "memory");
}
__device__ __forceinline__ void cpa_commit() {
    asm volatile("cp.async.commit_group;" ::: "memory");
}
__device__ __forceinline__ void cpa_wait2() {
    asm volatile("cp.async.wait_group 2;" ::: "memory");
}
__device__ __forceinline__ void cpa_wait0() {
    asm volatile("cp.async.wait_group 0;" ::: "memory");
}
__device__ __forceinline__ void mma_f16(float* d, const uint32_t* a, const uint32_t* b) {
    asm volatile(
        "mma.sync.aligned.m16n8k16.row.col.f32.f16.f16.f32 "
        "{%0,%1,%2,%3}, {%4,%5,%6,%7}, {%8,%9}, {%0,%1,%2,%3};"
        : "+f"(d[0]), "+f"(d[1]), "+f"(d[2]), "+f"(d[3])
        : "r"(a[0]), "r"(a[1]), "r"(a[2]), "r"(a[3]),
          "r"(b[0]), "r"(b[1]));
}

// ---------------------------------------------------------------------------
// FP16 mma.sync GEMM (R16, passing): CTA 128x128, BK=32, 128 thr (2x2 warps),
// warp 64x64, 4-stage cp.async, wait->sync->issue->compute, 2 CTAs/SM.
// HOUT: fp16 C via smem-staged coalesced stores. SCAT: row m -> C row win[m].
// ---------------------------------------------------------------------------
#define BM 128
#define BN 128
#define BK 32
#define A_STAGE_W 2048
#define B_STAGE_W 2048
#define ST_W (A_STAGE_W + B_STAGE_W)     // 4096 words / stage
#define NSTAGE 4
#define SMEM_BYTES (NSTAGE * ST_W * 4)   // 65536
#define CSTG_STRIDE 68

template<bool HOUT, bool SCAT>
__global__ __launch_bounds__(128, 2)
void mma_gemm_h(const __half* __restrict__ A, const __half* __restrict__ B,
                void* __restrict__ Cv, const int* __restrict__ win, int N)
{
    extern __shared__ char smem[];
    const uint32_t sb = smem_u32(smem);
    uint32_t* smw = (uint32_t*)smem;

    const int tid  = threadIdx.x;
    const int bx   = blockIdx.x, by = blockIdx.y;
    const int warp = tid >> 5, lane = tid & 31;
    const int wm   = warp >> 1, wn = warp & 1;
    const int g    = lane >> 2, t = lane & 3;

    const __half* Asrc[4];
    uint32_t a_dst[4];
    #pragma unroll
    for (int j = 0; j < 4; j++) {
        int p  = tid + 128 * j;
        int ca = p >> 5;
        int rg = ca >> 1, jk = ca & 1;
        Asrc[j] = A + ((size_t)(by * 8 + rg) * KT16 + jk) * 256 + (p & 31) * 8;
        a_dst[j] = (uint32_t)p * 16;
    }
    const __half* Bsrc[4];
    uint32_t b_dst[4];
    #pragma unroll
    for (int j = 0; j < 4; j++) {
        int ngl = j >> 1, jk = j & 1;
        Bsrc[j] = B + ((size_t)(bx * 2 + ngl) * KT16 + jk) * 1024 + tid * 8;
        b_dst[j] = (uint32_t)(A_STAGE_W * 4) + (uint32_t)(j * 2048 + tid * 16);
    }

    const uint32_t a_base = (uint32_t)(lane * 4);
    const int gs = g ^ (2 * t);
    const uint32_t b_base = (uint32_t)(A_STAGE_W + t * 128 + gs * 4);

    float acc[4][8][4];
    #pragma unroll
    for (int mt = 0; mt < 4; mt++)
        #pragma unroll
        for (int nt = 0; nt < 8; nt++)
            #pragma unroll
            for (int i = 0; i < 4; i++) acc[mt][nt][i] = 0.f;

    const int NIT = KDIM / BK;   // 40

    #pragma unroll
    for (int s = 0; s < NSTAGE - 1; s++) {
        const uint32_t so = sb + s * (ST_W * 4);
        #pragma unroll
        for (int j = 0; j < 4; j++)
            cpa16(so + a_dst[j], Asrc[j] + (size_t)s * 512);
        #pragma unroll
        for (int j = 0; j < 4; j++)
            cpa16(so + b_dst[j], Bsrc[j] + (size_t)s * 2048);
        cpa_commit();
    }

    for (int i = 0; i < NIT; i++) {
        const int s = i & 3;
        cpa_wait2();
        __syncthreads();

        if (i + NSTAGE - 1 < NIT) {
            const int s3 = (i + NSTAGE - 1) & 3;
            const uint32_t so = sb + s3 * (ST_W * 4);
            const size_t ko = (size_t)(i + NSTAGE - 1);
            #pragma unroll
            for (int j = 0; j < 4; j++)
                cpa16(so + a_dst[j], Asrc[j] + ko * 512);
            #pragma unroll
            for (int j = 0; j < 4; j++)
                cpa16(so + b_dst[j], Bsrc[j] + ko * 2048);
        }
        cpa_commit();

        const uint32_t* As = smw + s * ST_W;
        #pragma unroll
        for (int ks = 0; ks < 2; ks++) {
            uint32_t af[4][4];
            #pragma unroll
            for (int mt = 0; mt < 4; mt++)
                *(uint4*)af[mt] = *(const uint4*)
                    (As + ((wm * 4 + mt) * 2 + ks) * 128 + a_base);
            uint32_t b0[8], b1[8];
            {
                const uint32_t* p = As + b_base + (wn * 2 + ks) * 512;
                *(uint4*)&b0[0] = *(const uint4*)(p);
                *(uint4*)&b0[4] = *(const uint4*)(p + 32);
                *(uint4*)&b1[0] = *(const uint4*)(p + 64);
                *(uint4*)&b1[4] = *(const uint4*)(p + 96);
            }
            #pragma unroll
            for (int mt = 0; mt < 4; mt++)
                #pragma unroll
                for (int nt = 0; nt < 8; nt++) {
                    uint32_t bb[2] = { b0[nt], b1[nt] };
                    mma_f16(acc[mt][nt], af[mt], bb);
                }
        }
    }

    if (HOUT) {
        cpa_wait0();
        __syncthreads();
        __half* stg = (__half*)smem;
        #pragma unroll
        for (int mt = 0; mt < 4; mt++) {
            const int r0 = wm * 64 + mt * 16 + g;
            #pragma unroll
            for (int nt = 0; nt < 8; nt++) {
                const int col = wn * 64 + nt * 8 + t * 2;
                *(__half2*)(stg + (size_t)r0 * (CSTG_STRIDE * 2) + col) =
                    __floats2half2_rn(acc[mt][nt][0], acc[mt][nt][1]);
                *(__half2*)(stg + (size_t)(r0 + 8) * (CSTG_STRIDE * 2) + col) =
                    __floats2half2_rn(acc[mt][nt][2], acc[mt][nt][3]);
            }
        }
        __syncthreads();
        __half* C = (__half*)Cv;
        #pragma unroll
        for (int pass = 0; pass < 8; pass++) {
            int row = pass * 16 + (tid >> 3);
            const uint4* srow = (const uint4*)(smw + (size_t)row * CSTG_STRIDE);
            uint4 v0 = srow[tid & 7];
            uint4 v1 = srow[(tid & 7) + 8];
            int gr = SCAT ? win[by * BM + row] : by * BM + row;
            uint4* Crow = (uint4*)(C + (size_t)gr * N + bx * BN);
            Crow[tid & 7]       = v0;
            Crow[(tid & 7) + 8] = v1;
        }
    } else {
        #pragma unroll
        for (int mt = 0; mt < 4; mt++) {
            const int m0 = by * BM + wm * 64 + mt * 16 + g;
            int r0 = SCAT ? win[m0]     : m0;
            int r1 = SCAT ? win[m0 + 8] : m0 + 8;
            float* C = (float*)Cv;
            #pragma unroll
            for (int nt = 0; nt < 8; nt++) {
                const int col = bx * BN + wn * 64 + nt * 8 + t * 2;
                *(float2*)(C + (size_t)r0 * N + col) =
                    make_float2(acc[mt][nt][0], acc[mt][nt][1]);
                *(float2*)(C + (size_t)r1 * N + col) =
                    make_float2(acc[mt][nt][2], acc[mt][nt][3]);
            }
        }
    }
}

// ---------------------------------------------------------------------------
// x -> gathered rows, fp16, A-frag layout (smem-staged, coalesced writes)
// ---------------------------------------------------------------------------
__global__ __launch_bounds__(256)
void cvt_x_gather_kernel(const float* __restrict__ x, __half* __restrict__ xt,
                         const int* __restrict__ win)
{
    __shared__ uint32_t st[KT16 * 128];
    const int mt  = blockIdx.x;
    const int tid = threadIdx.x;
    const int i   = tid >> 4;
    const float* src = x + (size_t)win[mt * 16 + i] * KDIM;

    #pragma unroll
    for (int j = 0; j < 20; j++) {
        int c4 = ((tid & 15) + 16 * j) * 4;
        float4 v = *(const float4*)(src + c4);
        int kt = c4 >> 4;
        int l  = (i & 7) * 4 + ((c4 >> 1) & 3);
        int r  = (i >> 3) + ((c4 >> 3) & 1) * 2;
        int off = kt * 128 + l * 4 + r;
        __half2 h0 = __floats2half2_rn(v.x, v.y);
        __half2 h1 = __floats2half2_rn(v.z, v.w);
        st[off]     = *(uint32_t*)&h0;
        st[off + 4] = *(uint32_t*)&h1;
    }
    __syncthreads();

    uint4* dst = (uint4*)(xt + (size_t)mt * KT16 * 256);
    const uint4* s4 = (const uint4*)st;
    #pragma unroll
    for (int j = 0; j < 10; j++)
        dst[tid + 256 * j] = s4[tid + 256 * j];
}

// ---------------------------------------------------------------------------
// Both weights -> fp16 B-frag layout in ONE launch.
// blockIdx.x < 60: W_qkv (N=3840); else W_proj (N=1280).
// ---------------------------------------------------------------------------
__global__ __launch_bounds__(256)
void cvt_w_frag_kernel(const float* __restrict__ Wq, __half* __restrict__ WFq,
                       const float* __restrict__ Wp, __half* __restrict__ WFp)
{
    __shared__ __half st[4096];
    int bxx = blockIdx.x;
    const float* W; __half* WF; int N; int ngl;
    if (bxx < 60) { W = Wq; WF = WFq; N = C3;    ngl = bxx; }
    else          { W = Wp; WF = WFp; N = C_DIM; ngl = bxx - 60; }
    const int kb  = blockIdx.y;
    const int tid = threadIdx.x;

    #pragma unroll
    for (int j = 0; j < 4; j++) {
        int idx  = tid + 256 * j;
        int krow = idx >> 4;
        int nc   = (idx & 15) * 4;
        int k = kb * 64 + krow;
        float4 v = *(const float4*)(W + (size_t)k * N + ngl * 64 + nc);
        int kk = k & 15, ktl = (k >> 4) & 3;
        int tt = (kk >> 1) & 3, hh = (kk >> 3) & 1, e = kk & 1;
        float vals[4] = { v.x, v.y, v.z, v.w };
        #pragma unroll
        for (int q2 = 0; q2 < 4; q2++) {
            int nn = nc + q2;
            int gg = (nn & 7) ^ (kk & 6);
            int qq = (nn >> 5) & 1, cc = (nn >> 3) & 3;
            int hoff = ktl * 1024 + ((((tt * 2 + hh) * 2 + qq) * 8 + gg) * 8 + cc * 2 + e);
            st[hoff] = __float2half_rn(vals[q2]);
        }
    }
    __syncthreads();

    uint4* dst = (uint4*)(WF + ((size_t)ngl * KT16 + kb * 4) * 1024);
    const uint4* s4 = (const uint4*)st;
    dst[tid]       = s4[tid];
    dst[tid + 256] = s4[tid + 256];
}

// ---------------------------------------------------------------------------
// Windowed attention, RoPE fused, fully vectorized (uint4/float4 everywhere).
// Reads fp16 qkv (window order); writes g_y in WINDOW order, frag layout.
// ---------------------------------------------------------------------------
#define QSTR 84   // smem row stride (floats): 16B-aligned, LDS.128 conflict-free

__global__ __launch_bounds__(256)
void attn_kernel(const __half* __restrict__ qkv, __half* __restrict__ y,
                 const int* __restrict__ win,
                 const float* __restrict__ cosp, const float* __restrict__ sinp)
{
    const int b = blockIdx.x >> 4;
    const int h = blockIdx.x & 15;

    __shared__ float qs[BLK][QSTR];
    __shared__ float ks[BLK][QSTR];
    __shared__ float vs[BLK][QSTR];
    __shared__ float os[BLK][QSTR];
    __shared__ float att[BLK][BLK + 1];
    __shared__ int   toks[BLK];

    const int tid = threadIdx.x;
    if (tid < BLK) toks[tid] = win[b * BLK + tid];
    __syncthreads();

    // ---- load + RoPE: 160 chunks of 8 halfs (i = row, c = chunk) ----
    if (tid < 160) {
        int i = tid / 10, c = tid % 10;
        size_t base = (size_t)(b * BLK + i) * C3 + (size_t)h * D_HEAD + c * 8;
        uint4 qv = *(const uint4*)(qkv + base);
        uint4 kv = *(const uint4*)(qkv + base + C_DIM);
        uint4 vv = *(const uint4*)(qkv + base + 2 * C_DIM);
        int tok = toks[i];
        const float4* cp = (const float4*)(cosp + (size_t)tok * D_HEAD + c * 8);
        const float4* sp = (const float4*)(sinp + (size_t)tok * D_HEAD + c * 8);
        float4 c0 = cp[0], c1 = cp[1];
        float4 s0 = sp[0], s1 = sp[1];

        float q[8], k[8], v[8], cc[8], ss[8];
        {
            const __half2* qh = (const __half2*)&qv;
            const __half2* kh = (const __half2*)&kv;
            const __half2* vh = (const __half2*)&vv;
            #pragma unroll
            for (int e = 0; e < 4; e++) {
                float2 f;
                f = __half22float2(qh[e]); q[2*e] = f.x; q[2*e+1] = f.y;
                f = __half22float2(kh[e]); k[2*e] = f.x; k[2*e+1] = f.y;
                f = __half22float2(vh[e]); v[2*e] = f.x; v[2*e+1] = f.y;
            }
            cc[0]=c0.x; cc[1]=c0.y; cc[2]=c0.z; cc[3]=c0.w;
            cc[4]=c1.x; cc[5]=c1.y; cc[6]=c1.z; cc[7]=c1.w;
            ss[0]=s0.x; ss[1]=s0.y; ss[2]=s0.z; ss[3]=s0.w;
            ss[4]=s1.x; ss[5]=s1.y; ss[6]=s1.z; ss[7]=s1.w;
        }
        float qr[8], kr[8];
        #pragma unroll
        for (int e = 0; e < 8; e++) {
            qr[e] = q[e] * cc[e] + k[e] * ss[e];
            kr[e] = k[e] * cc[e] - q[e] * ss[e];
        }
        *(float4*)&qs[i][c*8]     = make_float4(qr[0], qr[1], qr[2], qr[3]);
        *(float4*)&qs[i][c*8 + 4] = make_float4(qr[4], qr[5], qr[6], qr[7]);
        *(float4*)&ks[i][c*8]     = make_float4(kr[0], kr[1], kr[2], kr[3]);
        *(float4*)&ks[i][c*8 + 4] = make_float4(kr[4], kr[5], kr[6], kr[7]);
        *(float4*)&vs[i][c*8]     = make_float4(v[0], v[1], v[2], v[3]);
        *(float4*)&vs[i][c*8 + 4] = make_float4(v[4], v[5], v[6], v[7]);
    }
    __syncthreads();

    // ---- scores: thread (i,j), float4 dot (same accumulation order) ----
    {
        int i = tid >> 4, j = tid & 15;
        float sc = 0.f;
        #pragma unroll
        for (int c = 0; c < 20; c++) {
            float4 q4 = *(const float4*)&qs[i][c*4];
            float4 k4 = *(const float4*)&ks[j][c*4];
            sc += q4.x * k4.x;
            sc += q4.y * k4.y;
            sc += q4.z * k4.z;
            sc += q4.w * k4.w;
        }
        att[i][j] = sc * 0.11180339887498949f;   // 1/sqrt(80)
    }
    __syncthreads();

    if (tid < BLK) {
        float m = -1e30f;
        #pragma unroll
        for (int j = 0; j < BLK; j++) m = fmaxf(m, att[tid][j]);
        float sum = 0.f;
        #pragma unroll
        for (int j = 0; j < BLK; j++) {
            float e = __expf(att[tid][j] - m);
            att[tid][j] = e;
            sum += e;
        }
        float inv = 1.f / sum;
        #pragma unroll
        for (int j = 0; j < BLK; j++) att[tid][j] *= inv;
    }
    __syncthreads();

    // ---- output: 320 (i, c) float4 items ----
    for (int idx = tid; idx < 320; idx += 256) {
        int i = idx / 20, c = idx % 20;
        float4 a4 = make_float4(0.f, 0.f, 0.f, 0.f);
        #pragma unroll
        for (int j = 0; j < BLK; j++) {
            float a = att[i][j];
            float4 v4 = *(const float4*)&vs[j][c*4];
            a4.x += a * v4.x;
            a4.y += a * v4.y;
            a4.z += a * v4.z;
            a4.w += a * v4.w;
        }
        *(float4*)&os[i][c*4] = a4;
    }
    __syncthreads();

    // ---- coalesced frag-layout writes (WINDOW order) ----
    for (int idx = tid; idx < 5 * 128; idx += 256) {
        int ktl = idx >> 7;
        int w   = idx & 127;
        int l = w >> 2, r = w & 3;
        int i  = ((r & 1) << 3) | (l >> 2);
        int k0 = ((r >> 1) << 3) | ((l & 3) << 1);
        int d  = ktl * 16 + k0;
        __half2 v2 = __floats2half2_rn(os[i][d], os[i][d + 1]);
        *(__half2*)(y + ((size_t)b * KT16 + 5 * h + ktl) * 256 + (size_t)w * 2) = v2;
    }
}

// ---------------------------------------------------------------------------
extern "C" void kernel_launch(void* const* d_in, const int* in_sizes, int n_in,
                              void* d_out, int out_size)
{
    const float* x     = (const float*)d_in[0];
    const float* cosp  = (const float*)d_in[1];
    const float* sinp  = (const float*)d_in[2];
    const float* Wqkv  = (const float*)d_in[3];
    const float* Wproj = (const float*)d_in[4];
    const int*   win   = (const int*)  d_in[5];
    float* out = (float*)d_out;

    __half *qkv_ptr, *xt_ptr, *y_ptr, *wqkv_ptr, *wproj_ptr;
    cudaGetSymbolAddress((void**)&qkv_ptr,   g_qkv);
    cudaGetSymbolAddress((void**)&xt_ptr,    g_xt);
    cudaGetSymbolAddress((void**)&y_ptr,     g_y);
    cudaGetSymbolAddress((void**)&wqkv_ptr,  g_wqkvF);
    cudaGetSymbolAddress((void**)&wproj_ptr, g_wprojF);

    cudaFuncSetAttribute((const void*)mma_gemm_h<true, false>,
        cudaFuncAttributeMaxDynamicSharedMemorySize, SMEM_BYTES);
    cudaFuncSetAttribute((const void*)mma_gemm_h<false, true>,
        cudaFuncAttributeMaxDynamicSharedMemorySize, SMEM_BYTES);

    // 0) pre-permute inputs
    cvt_x_gather_kernel<<<NBLK, 256>>>(x, xt_ptr, win);
    cvt_w_frag_kernel<<<dim3(60 + 20, KT16 / 4), 256>>>(Wqkv, wqkv_ptr,
                                                        Wproj, wproj_ptr);

    // 1) QKV GEMM: g_qkv(fp16, window order) = g_xt @ W_qkv
    {
        dim3 grid(C3 / BN, S_TOK / BM);   // 30 x 128
        mma_gemm_h<true, false><<<grid, 128, SMEM_BYTES>>>(
            xt_ptr, wqkv_ptr, qkv_ptr, nullptr, C3);
    }

    // 2) Windowed attention (RoPE fused) -> g_y (fp16 A-frag, WINDOW order)
    attn_kernel<<<NBLK * 16, 256>>>(qkv_ptr, y_ptr, win, cosp, sinp);

    // 3) Output projection with inverse-permutation row scatter:
    //    out[win[m]] = g_y[m] @ W_proj
    {
        dim3 grid(C_DIM / BN, S_TOK / BM);  // 10 x 128
        mma_gemm_h<false, true><<<grid, 128, SMEM_BYTES>>>(
            y_ptr, wproj_ptr, out, win, C_DIM);
    }
}